// round 15
// baseline (speedup 1.0000x reference)
#include <cuda_runtime.h>
#include <cuda_bf16.h>
#include <math.h>
#include <stdint.h>

#define NM 10000
#define ND 552
#define LDA 560          // padded row length of augmented matrix (553 cols used)
#define NB 32
#define NPANEL 18        // 17*32 + 8 = 552
#define KSB 8            // k-split for F @ P
#define NCHUNK 313       // ceil(10000/32)
#define MS 46            // m-tiles [0,MS) -> HMMA kernel; [MS,79) -> FFMA kernel

// ---------------- device scratch (static; no allocation allowed) ----------------
__device__ float          g_Pt[(size_t)ND * NM];           // 22.1 MB  P transposed [j][m]
__device__ __nv_bfloat16  g_Fhi[(size_t)ND * NM];          // 11 MB
__device__ __nv_bfloat16  g_Flo[(size_t)ND * NM];          // 11 MB
__device__ float          g_Bpart[(size_t)KSB * ND * ND];  // 9.8 MB
__device__ float          g_Aaug[(size_t)ND * LDA];        // [A | r] -> LU factors (rows perm'd via g_rp)
__device__ float          g_rorig[ND];
__device__ float          g_tmp[ND];                       // x0 then x1
__device__ int            g_rp[ND];                        // row permutation (logical->physical)
__device__ float          g_ld[1];
__device__ float          g_y[NM];
__device__ float          g_z[NM];
__device__ float          g_resid[ND];

// ===================== helpers ==================
__device__ __forceinline__ uint32_t smem_u32(const void* p) {
    uint32_t a;
    asm("{ .reg .u64 t; cvta.to.shared.u64 t, %1; cvt.u32.u64 %0, t; }" : "=r"(a) : "l"(p));
    return a;
}

__device__ __forceinline__ void ldx4(uint32_t* r, uint32_t addr) {
    asm volatile("ldmatrix.sync.aligned.m8n8.x4.shared.b16 {%0,%1,%2,%3}, [%4];"
                 : "=r"(r[0]), "=r"(r[1]), "=r"(r[2]), "=r"(r[3]) : "r"(addr));
}

__device__ __forceinline__ void mma16816(float* c, const uint32_t* a, uint32_t b0, uint32_t b1) {
    asm volatile(
        "mma.sync.aligned.m16n8k16.row.col.f32.bf16.bf16.f32 "
        "{%0,%1,%2,%3}, {%4,%5,%6,%7}, {%8,%9}, {%0,%1,%2,%3};"
        : "+f"(c[0]), "+f"(c[1]), "+f"(c[2]), "+f"(c[3])
        : "r"(a[0]), "r"(a[1]), "r"(a[2]), "r"(a[3]), "r"(b0), "r"(b1));
}

__device__ __forceinline__ void split2(float a, float b, uint32_t& hv, uint32_t& lv) {
    __nv_bfloat16 ha = __float2bfloat16(a), hb = __float2bfloat16(b);
    __nv_bfloat162 hh; hh.x = ha; hh.y = hb;
    hv = *(uint32_t*)&hh;
    __nv_bfloat162 ll;
    ll.x = __float2bfloat16(a - __bfloat162float(ha));
    ll.y = __float2bfloat16(b - __bfloat162float(hb));
    lv = *(uint32_t*)&ll;
}

__device__ __forceinline__ void cpasync16(uint32_t dst, const void* src, bool pred) {
    int sz = pred ? 16 : 0;
    asm volatile("cp.async.cg.shared.global [%0], [%1], 16, %2;"
                 :: "r"(dst), "l"(src), "r"(sz) : "memory");
}
#define CP_COMMIT() asm volatile("cp.async.commit_group;" ::: "memory")
#define CP_WAIT1()  asm volatile("cp.async.wait_group 1;" ::: "memory")

// per-stage layout (bytes): Ahi 0, Alo 10240, Bhi 20480, Blo 30720; stage stride 40960
#define PSTG 40960

// kBmma static layout
#define SM_BYTES 40960
#define A_LO_OFF 10240
#define B_HI_OFF 20480
#define B_LO_OFF 30720

// ============================ F -> bf16 hi/lo split ==========================
__global__ void kFsplit(const float* __restrict__ F) {
    int idx = blockIdx.x * 256 + threadIdx.x;
    if (idx >= ND * NM) return;
    float f = F[idx];
    __nv_bfloat16 h = __float2bfloat16(f);
    g_Fhi[idx] = h;
    g_Flo[idx] = __float2bfloat16(f - __bfloat162float(h));
}

// tiny: init row permutation
__global__ void kInit() {
    int i = blockIdx.x * 256 + threadIdx.x;
    if (i < ND) g_rp[i] = i;
}

// =====================================================================
// kPmma: Pt[j][m] = (s2*exp(c*D)) @ F^T for m-tiles [0, MS)  (HMMA path)
// =====================================================================
__global__ __launch_bounds__(256, 1) void kPmma(const float* __restrict__ Dm,
                                                const float* __restrict__ lsp,
                                                const float* __restrict__ sgp) {
    extern __shared__ __align__(16) char sm[];
    const uint32_t sb = smem_u32(sm);

    const int tid = threadIdx.x, lane = tid & 31, wid = tid >> 5;
    const int m0 = blockIdx.x * 128, j0 = blockIdx.y * 128;

    const float l = lsp[0];
    const float cexp = -0.5f / (l * l);
    const float s2 = sgp[0] * sgp[0];

    const int lr = tid >> 1, lk = (tid & 1) * 16;
    const bool mval = (m0 + lr) < NM;
    const bool nval = (j0 + lr) < ND;
    const int jrow = nval ? (j0 + lr) : (ND - 1);
    const float* Dp = Dm + (size_t)(m0 + lr) * NM + lk;
    const __nv_bfloat16* Fh = g_Fhi + (size_t)jrow * NM + lk;
    const __nv_bfloat16* Fl = g_Flo + (size_t)jrow * NM + lk;

    const uint32_t sA = (uint32_t)(lr * 40 + lk) * 2;

    float4 dv[4];
    bool dok[4];

#define LOADD(ch)                                                             \
    {                                                                         \
        int _k0 = (ch) * 32;                                                  \
        _Pragma("unroll")                                                     \
        for (int i = 0; i < 4; i++) {                                         \
            int kk = _k0 + lk + i * 4;                                        \
            dok[i] = mval && (kk < NM);                                       \
            dv[i] = dok[i] ? *(const float4*)(Dp + _k0 + i * 4)               \
                           : make_float4(0.f, 0.f, 0.f, 0.f);                 \
        }                                                                     \
    }

#define ISSUEF(ch, s)                                                         \
    {                                                                         \
        int _k0 = (ch) * 32;                                                  \
        bool ok  = nval && (_k0 + lk < NM);                                   \
        bool ok2 = nval && (_k0 + lk + 8 < NM);                               \
        uint32_t dB = sb + (s) * PSTG + 20480 + sA;                           \
        cpasync16(dB,              Fh + _k0,     ok);                         \
        cpasync16(dB + 16,         Fh + _k0 + 8, ok2);                        \
        cpasync16(dB + 10240,      Fl + _k0,     ok);                         \
        cpasync16(dB + 10240 + 16, Fl + _k0 + 8, ok2);                        \
    }

#define STSA(s)                                                               \
    {                                                                         \
        char* stg = sm + (s) * PSTG;                                          \
        _Pragma("unroll")                                                     \
        for (int i = 0; i < 4; i++) {                                         \
            float e0 = dok[i] ? s2 * __expf(cexp * dv[i].x) : 0.f;            \
            float e1 = dok[i] ? s2 * __expf(cexp * dv[i].y) : 0.f;            \
            float e2 = dok[i] ? s2 * __expf(cexp * dv[i].z) : 0.f;            \
            float e3 = dok[i] ? s2 * __expf(cexp * dv[i].w) : 0.f;            \
            uint32_t h01, l01, h23, l23;                                      \
            split2(e0, e1, h01, l01);                                         \
            split2(e2, e3, h23, l23);                                         \
            *(uint2*)(stg + sA + i * 8)         = make_uint2(h01, h23);       \
            *(uint2*)(stg + 10240 + sA + i * 8) = make_uint2(l01, l23);       \
        }                                                                     \
    }

    const int wm = (wid & 3) * 32, wn = (wid >> 2) * 64;
    const uint32_t aAoff = (uint32_t)((wm + (lane & 15)) * 40 + ((lane >> 4) & 1) * 8) * 2;
    const uint32_t aBoff = (uint32_t)((wn + ((lane >> 4) << 3) + (lane & 7)) * 40
                                      + ((lane >> 3) & 1) * 8) * 2;

    float acc[2][8][4];
#pragma unroll
    for (int a = 0; a < 2; a++)
#pragma unroll
        for (int b = 0; b < 8; b++)
#pragma unroll
            for (int d = 0; d < 4; d++) acc[a][b][d] = 0.f;

    LOADD(0);
    ISSUEF(0, 0); CP_COMMIT();
    STSA(0);
    LOADD(1);
    ISSUEF(1, 1); CP_COMMIT();
    CP_WAIT1();
    __syncthreads();

    for (int ch = 0; ch < NCHUNK; ++ch) {
        const int s = ch & 1;
        const uint32_t base = sb + s * PSTG;

#pragma unroll
        for (int kst = 0; kst < 2; ++kst) {
            uint32_t ah[2][4], al[2][4];
#pragma unroll
            for (int mt = 0; mt < 2; ++mt) {
                uint32_t o = aAoff + mt * 1280 + kst * 32;
                ldx4(ah[mt], base + o);
                ldx4(al[mt], base + 10240 + o);
            }
#pragma unroll
            for (int nh = 0; nh < 2; ++nh) {
                uint32_t bh[2][4], bl[2][4];
#pragma unroll
                for (int ng = 0; ng < 2; ++ng) {
                    uint32_t o = aBoff + nh * 2560 + ng * 1280 + kst * 32;
                    ldx4(bh[ng], base + 20480 + o);
                    ldx4(bl[ng], base + 30720 + o);
                }
#pragma unroll
                for (int mt = 0; mt < 2; mt++)
#pragma unroll
                    for (int nt = 0; nt < 4; nt++) {
                        float* cc = acc[mt][nh * 4 + nt];
                        uint32_t b0h = bh[nt >> 1][(nt & 1) * 2];
                        uint32_t b1h = bh[nt >> 1][(nt & 1) * 2 + 1];
                        uint32_t b0l = bl[nt >> 1][(nt & 1) * 2];
                        uint32_t b1l = bl[nt >> 1][(nt & 1) * 2 + 1];
                        mma16816(cc, ah[mt], b0h, b1h);
                        mma16816(cc, ah[mt], b0l, b1l);
                        mma16816(cc, al[mt], b0h, b1h);
                    }
            }
        }
        __syncthreads();

        if (ch + 2 < NCHUNK) ISSUEF(ch + 2, s);
        CP_COMMIT();
        if (ch + 1 < NCHUNK) STSA(s ^ 1);
        if (ch + 2 < NCHUNK) LOADD(ch + 2);
        CP_WAIT1();
        __syncthreads();
    }

    float* stg = (float*)sm;
#pragma unroll
    for (int h = 0; h < 2; ++h) {
        __syncthreads();
        if (((wid & 3) >> 1) == h) {
            const int rb = wm - h * 64 + (lane >> 2);
            const int cb = 2 * (lane & 3);
#pragma unroll
            for (int mt = 0; mt < 2; mt++)
#pragma unroll
                for (int nt = 0; nt < 8; nt++) {
                    int r = rb + mt * 16;
                    int c = wn + ((nt >> 2) * 32) + ((nt & 3) * 8) + cb;
                    stg[(c + 0) * 68 + r]     = acc[mt][nt][0];
                    stg[(c + 1) * 68 + r]     = acc[mt][nt][1];
                    stg[(c + 0) * 68 + r + 8] = acc[mt][nt][2];
                    stg[(c + 1) * 68 + r + 8] = acc[mt][nt][3];
                }
        }
        __syncthreads();
#pragma unroll 4
        for (int it = 0; it < 32; ++it) {
            int nr = it * 4 + (tid >> 6);
            int mc = tid & 63;
            int j = j0 + nr, m = m0 + h * 64 + mc;
            if (j < ND && m < NM) g_Pt[(size_t)j * NM + m] = stg[nr * 68 + mc];
        }
    }
}

// =====================================================================
// kPfma: fp32 SIMT GEMM (R7-proven) for m-tiles [MS, 79), writes g_Pt
// via smem transpose. Runs CONCURRENTLY with kPmma on the fma pipe.
// Tile 128m x 64j, K-chunk 16, 256 threads, 8x4 micro-tile.
// =====================================================================
__global__ __launch_bounds__(256) void kPfma(const float* __restrict__ D,
                                             const float* __restrict__ F,
                                             const float* __restrict__ lsp,
                                             const float* __restrict__ sgp)
{
    extern __shared__ float dyn2[];
    float (*Ds)[132] = (float (*)[132])dyn2;              // 16 x 132
    float (*Fs)[68]  = (float (*)[68])(dyn2 + 16 * 132);  // 16 x 68

    const int tid = threadIdx.x;
    const int m0  = (MS + blockIdx.y) * 128;
    const int j0  = blockIdx.x * 64;

    const float l  = lsp[0];
    const float c  = -0.5f / (l * l);
    const float sg = sgp[0];
    const float s2 = sg * sg;

    const int trow = tid >> 4;      // 0..15 -> 8 rows each
    const int tcol = tid & 15;      // 0..15 -> 4 cols each

    const int q0  = tid * 2;
    const int ar0 = q0 >> 2,        ak0 = (q0 & 3) * 4;
    const int ar1 = (q0 + 1) >> 2,  ak1 = ((q0 + 1) & 3) * 4;
    const bool av0 = (m0 + ar0) < NM;
    const bool av1 = (m0 + ar1) < NM;
    const float* Dp0 = D + (size_t)(m0 + ar0) * NM + ak0;
    const float* Dp1 = D + (size_t)(m0 + ar1) * NM + ak1;

    const int fj = tid >> 2, fk = (tid & 3) * 4;
    const bool fv = (j0 + fj) < ND;
    const float* Fp = F + (size_t)(j0 + fj) * NM + fk;

    float acc[8][4];
#pragma unroll
    for (int i = 0; i < 8; i++)
#pragma unroll
        for (int j = 0; j < 4; j++) acc[i][j] = 0.f;

    for (int k0 = 0; k0 < NM; k0 += 16) {
        __syncthreads();
        float4 d0 = av0 ? *(const float4*)(Dp0 + k0) : make_float4(0.f, 0.f, 0.f, 0.f);
        float4 d1 = av1 ? *(const float4*)(Dp1 + k0) : make_float4(0.f, 0.f, 0.f, 0.f);
        float4 f  = fv  ? *(const float4*)(Fp  + k0) : make_float4(0.f, 0.f, 0.f, 0.f);

        Ds[ak0 + 0][ar0] = s2 * __expf(c * d0.x);
        Ds[ak0 + 1][ar0] = s2 * __expf(c * d0.y);
        Ds[ak0 + 2][ar0] = s2 * __expf(c * d0.z);
        Ds[ak0 + 3][ar0] = s2 * __expf(c * d0.w);
        Ds[ak1 + 0][ar1] = s2 * __expf(c * d1.x);
        Ds[ak1 + 1][ar1] = s2 * __expf(c * d1.y);
        Ds[ak1 + 2][ar1] = s2 * __expf(c * d1.z);
        Ds[ak1 + 3][ar1] = s2 * __expf(c * d1.w);

        Fs[fk + 0][fj] = f.x;
        Fs[fk + 1][fj] = f.y;
        Fs[fk + 2][fj] = f.z;
        Fs[fk + 3][fj] = f.w;
        __syncthreads();

#pragma unroll
        for (int kk = 0; kk < 16; kk++) {
            float4 a0 = *(const float4*)&Ds[kk][trow * 8];
            float4 a1 = *(const float4*)&Ds[kk][trow * 8 + 4];
            float4 b  = *(const float4*)&Fs[kk][tcol * 4];
            float av[8] = {a0.x, a0.y, a0.z, a0.w, a1.x, a1.y, a1.z, a1.w};
            float bv[4] = {b.x, b.y, b.z, b.w};
#pragma unroll
            for (int i = 0; i < 8; i++)
#pragma unroll
                for (int j = 0; j < 4; j++) acc[i][j] += av[i] * bv[j];
        }
    }

    // epilogue: transpose via smem (reuse buffer), coalesced Pt stores
    __syncthreads();
    float (*T)[133] = (float (*)[133])dyn2;   // 64 x 133
#pragma unroll
    for (int i = 0; i < 8; i++)
#pragma unroll
        for (int j = 0; j < 4; j++)
            T[tcol * 4 + j][trow * 8 + i] = acc[i][j];
    __syncthreads();
#pragma unroll 4
    for (int it = 0; it < 32; ++it) {
        int jr = it * 2 + (tid >> 7);
        int mc = tid & 127;
        int jj = j0 + jr, m = m0 + mc;
        if (jj < ND && m < NM) g_Pt[(size_t)jj * NM + m] = T[jr][mc];
    }
}

// =====================================================================
// kBmma: Bpart[z] = F @ P   (unchanged, passing)
// =====================================================================
__global__ __launch_bounds__(256, 1) void kBmma() {
    __shared__ __align__(16) char sm[SM_BYTES];
    __nv_bfloat16* Ahi = (__nv_bfloat16*)sm;
    __nv_bfloat16* Alo = (__nv_bfloat16*)(sm + A_LO_OFF);
    __nv_bfloat16* Bhi = (__nv_bfloat16*)(sm + B_HI_OFF);
    __nv_bfloat16* Blo = (__nv_bfloat16*)(sm + B_LO_OFF);
    const uint32_t sb = smem_u32(sm);

    const int tid = threadIdx.x, lane = tid & 31, wid = tid >> 5;
    const int i0 = blockIdx.x * 128, j0 = blockIdx.y * 128;
    const int z = blockIdx.z;
    const int c0 = z * 40;
    const int c1 = min(NCHUNK, c0 + 40);

    const int lr = tid >> 1, lk = (tid & 1) * 16;
    const bool ival = (i0 + lr) < ND;
    const bool jval = (j0 + lr) < ND;
    const __nv_bfloat16* Fh = g_Fhi + (size_t)(i0 + lr) * NM + lk;
    const __nv_bfloat16* Fl = g_Flo + (size_t)(i0 + lr) * NM + lk;
    const float* Pp = g_Pt + (size_t)(j0 + lr) * NM + lk;

    float4 pv[4];
    bool pok[4];
    uint4 fh[2], fl[2];

#define LOADCH_B(k0)                                                          \
    {                                                                         \
        _Pragma("unroll")                                                     \
        for (int i = 0; i < 2; i++) {                                         \
            int kk = (k0) + lk + i * 8;                                       \
            bool ok = ival && (kk < NM);                                      \
            fh[i] = ok ? *(const uint4*)(Fh + (k0) + i * 8) : make_uint4(0, 0, 0, 0); \
            fl[i] = ok ? *(const uint4*)(Fl + (k0) + i * 8) : make_uint4(0, 0, 0, 0); \
        }                                                                     \
        _Pragma("unroll")                                                     \
        for (int i = 0; i < 4; i++) {                                         \
            int kk = (k0) + lk + i * 4;                                       \
            pok[i] = jval && (kk < NM);                                       \
            pv[i] = pok[i] ? *(const float4*)(Pp + (k0) + i * 4)              \
                           : make_float4(0.f, 0.f, 0.f, 0.f);                 \
        }                                                                     \
    }

    const int sA = lr * 40 + lk;
    const int wm = (wid & 3) * 32, wn = (wid >> 2) * 64;
    const uint32_t aAoff = (uint32_t)((wm + (lane & 15)) * 40 + ((lane >> 4) & 1) * 8) * 2;
    const uint32_t aBoff = (uint32_t)((wn + ((lane >> 4) << 3) + (lane & 7)) * 40
                                      + ((lane >> 3) & 1) * 8) * 2;

    float acc[2][8][4];
#pragma unroll
    for (int a = 0; a < 2; a++)
#pragma unroll
        for (int b = 0; b < 8; b++)
#pragma unroll
            for (int d = 0; d < 4; d++) acc[a][b][d] = 0.f;

    LOADCH_B(c0 * 32);

    for (int ch = c0; ch < c1; ++ch) {
        *(uint4*)(Ahi + sA) = fh[0];
        *(uint4*)(Ahi + sA + 8) = fh[1];
        *(uint4*)(Alo + sA) = fl[0];
        *(uint4*)(Alo + sA + 8) = fl[1];
#pragma unroll
        for (int i = 0; i < 4; i++) {
            uint32_t h01, l01, h23, l23;
            split2(pv[i].x, pv[i].y, h01, l01);
            split2(pv[i].z, pv[i].w, h23, l23);
            *(uint2*)(Bhi + sA + i * 4) = make_uint2(h01, h23);
            *(uint2*)(Blo + sA + i * 4) = make_uint2(l01, l23);
        }
        __syncthreads();

        if (ch + 1 < c1) LOADCH_B((ch + 1) * 32);

#pragma unroll
        for (int kst = 0; kst < 2; ++kst) {
            uint32_t ah[2][4], al[2][4];
#pragma unroll
            for (int mt = 0; mt < 2; ++mt) {
                uint32_t o = aAoff + mt * 1280 + kst * 32;
                ldx4(ah[mt], sb + o);
                ldx4(al[mt], sb + A_LO_OFF + o);
            }
#pragma unroll
            for (int nh = 0; nh < 2; ++nh) {
                uint32_t bh[2][4], bl[2][4];
#pragma unroll
                for (int ng = 0; ng < 2; ++ng) {
                    uint32_t o = aBoff + nh * 2560 + ng * 1280 + kst * 32;
                    ldx4(bh[ng], sb + B_HI_OFF + o);
                    ldx4(bl[ng], sb + B_LO_OFF + o);
                }
#pragma unroll
                for (int mt = 0; mt < 2; mt++)
#pragma unroll
                    for (int nt = 0; nt < 4; nt++) {
                        float* cc = acc[mt][nh * 4 + nt];
                        uint32_t b0h = bh[nt >> 1][(nt & 1) * 2];
                        uint32_t b1h = bh[nt >> 1][(nt & 1) * 2 + 1];
                        uint32_t b0l = bl[nt >> 1][(nt & 1) * 2];
                        uint32_t b1l = bl[nt >> 1][(nt & 1) * 2 + 1];
                        mma16816(cc, ah[mt], b0h, b1h);
                        mma16816(cc, ah[mt], b0l, b1l);
                        mma16816(cc, al[mt], b0h, b1h);
                    }
            }
        }
        __syncthreads();
    }

    float* Bp = g_Bpart + (size_t)z * ND * ND;
    const int rb = i0 + wm + (lane >> 2);
    const int cb = j0 + wn + 2 * (lane & 3);
#pragma unroll
    for (int mt = 0; mt < 2; mt++)
#pragma unroll
        for (int nt = 0; nt < 8; nt++) {
            int i = rb + mt * 16;
            int c = cb + (nt >> 2) * 32 + (nt & 3) * 8;
            if (c < ND) {
                if (i < ND)
                    *(float2*)(Bp + (size_t)i * ND + c) = make_float2(acc[mt][nt][0], acc[mt][nt][1]);
                if (i + 8 < ND)
                    *(float2*)(Bp + (size_t)(i + 8) * ND + c) = make_float2(acc[mt][nt][2], acc[mt][nt][3]);
            }
        }
}

// combine k-split partials + data_cov into Aaug
__global__ void kC(const float* __restrict__ dcov) {
    int idx = blockIdx.x * 256 + threadIdx.x;
    if (idx >= ND * ND) return;
    float s = dcov[idx];
#pragma unroll
    for (int zz = 0; zz < KSB; zz++) s += g_Bpart[(size_t)zz * ND * ND + idx];
    int i = idx / ND, j = idx - i * ND;
    g_Aaug[i * LDA + j] = s;
}

// prior misfit r = d_obs - m0 * rowsum(F)
__global__ __launch_bounds__(256) void kR(const float* __restrict__ F,
                                          const float* __restrict__ dobs,
                                          const float* __restrict__ m0p) {
    __shared__ float red[8];
    const int i = blockIdx.x;
    const float* row = F + (size_t)i * NM;
    float s = 0.f;
    for (int t = threadIdx.x; t < NM; t += 256) s += row[t];
#pragma unroll
    for (int o = 16; o; o >>= 1) s += __shfl_down_sync(0xffffffffu, s, o);
    if ((threadIdx.x & 31) == 0) red[threadIdx.x >> 5] = s;
    __syncthreads();
    if (threadIdx.x == 0) {
        float tot = 0.f;
#pragma unroll
        for (int w = 0; w < 8; w++) tot += red[w];
        float r = dobs[i] - m0p[0] * tot;
        g_Aaug[i * LDA + ND] = r;
        g_rorig[i] = r;
    }
}

// =====================================================================
// kLU: panel factor (perm-vector pivoting) + fused TRSM (padded Ls)
// =====================================================================
__global__ __launch_bounds__(512) void kLU(int p0, int pw) {
    extern __shared__ float dyn[];
    const int tid = threadIdx.x, lane = tid & 31, wid = tid >> 5;
    const int nrows = ND - p0;
    float* sp  = dyn;
    int*   srp = (int*)(dyn + nrows * pw);

    __shared__ float s_pv;
    __shared__ float Ls[32][33];

    for (int i = tid; i < nrows; i += 512) srp[i] = g_rp[p0 + i];
    __syncthreads();
    for (int idx = tid; idx < nrows * pw; idx += 512)
        sp[idx] = g_Aaug[(size_t)srp[idx / pw] * LDA + p0 + (idx % pw)];

    for (int j = 0; j < pw; j++) {
        __syncthreads();
        if (wid == 0) {
            float best = -1.f; int bi = j;
            for (int i = j + lane; i < nrows; i += 32) {
                float v = fabsf(sp[i * pw + j]);
                if (v > best) { best = v; bi = i; }
            }
#pragma unroll
            for (int o = 16; o; o >>= 1) {
                float ov = __shfl_down_sync(0xffffffffu, best, o);
                int   oi = __shfl_down_sync(0xffffffffu, bi,   o);
                if (ov > best) { best = ov; bi = oi; }
            }
            int piv = __shfl_sync(0xffffffffu, bi, 0);
            if (piv != j) {
                if (lane < pw) {
                    float t = sp[j * pw + lane];
                    sp[j * pw + lane] = sp[piv * pw + lane];
                    sp[piv * pw + lane] = t;
                }
                if (lane == 0) { int t = srp[j]; srp[j] = srp[piv]; srp[piv] = t; }
            }
            __syncwarp();
            if (lane == 0) s_pv = sp[j * pw + j];
        }
        __syncthreads();
        const float inv = 1.f / s_pv;
        for (int i = j + 1 + tid; i < nrows; i += 512) {
            float lij = sp[i * pw + j] * inv;
            sp[i * pw + j] = lij;
            for (int jj = j + 1; jj < pw; jj++)
                sp[i * pw + jj] -= lij * sp[j * pw + jj];
        }
    }
    __syncthreads();

    for (int idx = tid; idx < 32 * 33; idx += 512) ((float*)Ls)[idx] = 0.f;
    __syncthreads();
    for (int idx = tid; idx < nrows * pw; idx += 512)
        g_Aaug[(size_t)srp[idx / pw] * LDA + p0 + (idx % pw)] = sp[idx];
    for (int i = tid; i < nrows; i += 512) g_rp[p0 + i] = srp[i];
    for (int idx = tid; idx < pw * pw; idx += 512)
        Ls[idx / pw][idx % pw] = sp[(idx / pw) * pw + (idx % pw)];
    __syncthreads();

    for (int c = p0 + pw + tid; c <= ND; c += 512) {
        float v[32];
#pragma unroll
        for (int i = 0; i < 32; i++)
            v[i] = (i < pw) ? g_Aaug[(size_t)srp[i] * LDA + c] : 0.f;
#pragma unroll
        for (int k = 0; k < 32; k++) {
            if (k >= pw) break;
            float vk = v[k];
#pragma unroll
            for (int i = 0; i < 32; i++)
                if (i > k) v[i] -= Ls[i][k] * vk;
        }
#pragma unroll
        for (int i = 0; i < 32; i++)
            if (i < pw) g_Aaug[(size_t)srp[i] * LDA + c] = v[i];
    }
}

// A22 -= L21 @ U12  (rows via g_rp)
__global__ __launch_bounds__(256) void kG(int p0, int pw) {
    __shared__ float Ls[32][33];
    __shared__ float Us[32][36];
    __shared__ int   rmap[32];
    const int tid = threadIdx.x;
    const int r0  = p0 + pw;
    const int gi0 = r0 + blockIdx.x * 32;
    const int gj0 = r0 + blockIdx.y * 32;

    if (tid < 32) rmap[tid] = (gi0 + tid < ND) ? g_rp[gi0 + tid] : 0;
    __syncthreads();

    for (int idx = tid; idx < 32 * 32; idx += 256) {
        int i = idx >> 5, k = idx & 31;
        float v = 0.f;
        if (k < pw && gi0 + i < ND) v = g_Aaug[(size_t)rmap[i] * LDA + p0 + k];
        Ls[i][k] = v;
    }
    for (int idx = tid; idx < 32 * 32; idx += 256) {
        int k = idx >> 5, jn = idx & 31;
        float v = 0.f;
        if (k < pw && gj0 + jn <= ND) v = g_Aaug[(size_t)g_rp[p0 + k] * LDA + gj0 + jn];
        Us[k][jn] = v;
    }
    __syncthreads();

    const int mi = tid >> 3;
    const int nj = (tid & 7) * 4;
    float a0 = 0.f, a1 = 0.f, a2 = 0.f, a3 = 0.f;
    for (int k = 0; k < pw; k++) {
        float a = Ls[mi][k];
        a0 += a * Us[k][nj + 0];
        a1 += a * Us[k][nj + 1];
        a2 += a * Us[k][nj + 2];
        a3 += a * Us[k][nj + 3];
    }
    const int gi = gi0 + mi;
    if (gi < ND) {
        float* rowp = g_Aaug + (size_t)rmap[mi] * LDA;
        if (gj0 + nj + 0 <= ND) rowp[gj0 + nj + 0] -= a0;
        if (gj0 + nj + 1 <= ND) rowp[gj0 + nj + 1] -= a1;
        if (gj0 + nj + 2 <= ND) rowp[gj0 + nj + 2] -= a2;
        if (gj0 + nj + 3 <= ND) rowp[gj0 + nj + 3] -= a3;
    }
}

// back-substitution (warp-shuffle diag blocks) -> x0; logdet -> g_ld
__global__ __launch_bounds__(512) void kBack(void) {
    __shared__ float x[ND];
    __shared__ float ub[32][33];
    __shared__ float red[16];
    const int tid = threadIdx.x;

    for (int i = tid; i < ND; i += 512) x[i] = g_Aaug[(size_t)g_rp[i] * LDA + ND];
    float ld = 0.f;
    for (int k = tid; k < ND; k += 512) ld += logf(fabsf(g_Aaug[(size_t)g_rp[k] * LDA + k]));
    __syncthreads();

    for (int pb = NPANEL - 1; pb >= 0; pb--) {
        const int p0 = pb * NB;
        const int pw = (pb == NPANEL - 1) ? (ND - p0) : NB;
        for (int idx = tid; idx < pw * pw; idx += 512)
            ub[idx / pw][idx % pw] = g_Aaug[(size_t)g_rp[p0 + idx / pw] * LDA + p0 + (idx % pw)];
        __syncthreads();
        if (tid < 32) {
            float xi = (tid < pw) ? x[p0 + tid] : 0.f;
            for (int j = pw - 1; j >= 0; j--) {
                if (tid == j) xi /= ub[j][j];
                float xj = __shfl_sync(0xffffffffu, xi, j);
                if (tid < j) xi -= ub[tid][j] * xj;
            }
            if (tid < pw) x[p0 + tid] = xi;
        }
        __syncthreads();
        for (int i = tid; i < p0; i += 512) {
            float s = 0.f;
            for (int j = 0; j < pw; j++)
                s += g_Aaug[(size_t)g_rp[i] * LDA + p0 + j] * x[p0 + j];
            x[i] -= s;
        }
        __syncthreads();
    }

#pragma unroll
    for (int o = 16; o; o >>= 1) ld += __shfl_down_sync(0xffffffffu, ld, o);
    if ((tid & 31) == 0) red[tid >> 5] = ld;
    __syncthreads();
    if (tid == 0) {
        float tl = 0.f;
        for (int w = 0; w < 16; w++) tl += red[w];
        g_ld[0] = tl;
    }
    for (int i = tid; i < ND; i += 512) g_tmp[i] = x[i];
}

// ===================== iterative refinement: exact fp32 operator =============
__global__ __launch_bounds__(256) void kAy(const float* __restrict__ F) {
    __shared__ float sx[ND];
    const int tid = threadIdx.x;
    for (int i = tid; i < ND; i += 256) sx[i] = g_tmp[i];
    __syncthreads();
    const int m = blockIdx.x * 256 + tid;
    if (m >= NM) return;
    float s = 0.f;
#pragma unroll 4
    for (int i = 0; i < ND; i++) s += F[(size_t)i * NM + m] * sx[i];
    g_y[m] = s;
}

__global__ __launch_bounds__(256) void kAz(const float* __restrict__ Dm,
                                           const float* __restrict__ lsp,
                                           const float* __restrict__ sgp) {
    const int tid = threadIdx.x, lane = tid & 31, warp = tid >> 5;
    const int row = blockIdx.x * 8 + warp;
    if (row >= NM) return;
    const float l = lsp[0];
    const float c = -0.5f / (l * l);
    const float s2 = sgp[0] * sgp[0];
    const float* dr = Dm + (size_t)row * NM;
    float s = 0.f;
    for (int k = lane; k < NM; k += 32) s += __expf(c * dr[k]) * __ldg(&g_y[k]);
#pragma unroll
    for (int o = 16; o; o >>= 1) s += __shfl_down_sync(0xffffffffu, s, o);
    if (lane == 0) g_z[row] = s2 * s;
}

__global__ __launch_bounds__(256) void kAw(const float* __restrict__ F,
                                           const float* __restrict__ dcov) {
    __shared__ float red[8];
    const int i = blockIdx.x;
    const int tid = threadIdx.x;
    float s = 0.f;
    const float* fr = F + (size_t)i * NM;
    for (int m = tid; m < NM; m += 256) s += fr[m] * g_z[m];
    const float* cr = dcov + (size_t)i * ND;
    for (int j = tid; j < ND; j += 256) s += cr[j] * g_tmp[j];
#pragma unroll
    for (int o = 16; o; o >>= 1) s += __shfl_down_sync(0xffffffffu, s, o);
    if ((tid & 31) == 0) red[tid >> 5] = s;
    __syncthreads();
    if (tid == 0) {
        float tot = 0.f;
#pragma unroll
        for (int w = 0; w < 8; w++) tot += red[w];
        g_resid[i] = g_rorig[i] - tot;
    }
}

// solve LU dx = P resid; x1 = x0 + dx; out[0] = logdet + r^T x1; g_tmp = x1
__global__ __launch_bounds__(512) void kSolve(float* __restrict__ out) {
    __shared__ float x[ND];
    __shared__ float Bs[32][33];
    __shared__ float red[16];
    const int tid = threadIdx.x;

    for (int i = tid; i < ND; i += 512) x[i] = g_resid[g_rp[i]];
    __syncthreads();

    for (int pb = 0; pb < NPANEL; pb++) {
        const int p0 = pb * NB;
        const int pw = (pb == NPANEL - 1) ? (ND - p0) : NB;
        for (int idx = tid; idx < pw * pw; idx += 512)
            Bs[idx / pw][idx % pw] = g_Aaug[(size_t)g_rp[p0 + idx / pw] * LDA + p0 + (idx % pw)];
        __syncthreads();
        if (tid < 32) {
            float xi = (tid < pw) ? x[p0 + tid] : 0.f;
            for (int j = 0; j < pw; j++) {
                float xj = __shfl_sync(0xffffffffu, xi, j);
                if (tid > j && tid < pw) xi -= Bs[tid][j] * xj;
            }
            if (tid < pw) x[p0 + tid] = xi;
        }
        __syncthreads();
        for (int i = p0 + pw + tid; i < ND; i += 512) {
            float s = 0.f;
            for (int j = 0; j < pw; j++)
                s += g_Aaug[(size_t)g_rp[i] * LDA + p0 + j] * x[p0 + j];
            x[i] -= s;
        }
        __syncthreads();
    }

    for (int pb = NPANEL - 1; pb >= 0; pb--) {
        const int p0 = pb * NB;
        const int pw = (pb == NPANEL - 1) ? (ND - p0) : NB;
        for (int idx = tid; idx < pw * pw; idx += 512)
            Bs[idx / pw][idx % pw] = g_Aaug[(size_t)g_rp[p0 + idx / pw] * LDA + p0 + (idx % pw)];
        __syncthreads();
        if (tid < 32) {
            float xi = (tid < pw) ? x[p0 + tid] : 0.f;
            for (int j = pw - 1; j >= 0; j--) {
                if (tid == j) xi /= Bs[j][j];
                float xj = __shfl_sync(0xffffffffu, xi, j);
                if (tid < j) xi -= Bs[tid][j] * xj;
            }
            if (tid < pw) x[p0 + tid] = xi;
        }
        __syncthreads();
        for (int i = tid; i < p0; i += 512) {
            float s = 0.f;
            for (int j = 0; j < pw; j++)
                s += g_Aaug[(size_t)g_rp[i] * LDA + p0 + j] * x[p0 + j];
            x[i] -= s;
        }
        __syncthreads();
    }

    float dp = 0.f;
    for (int i = tid; i < ND; i += 512) {
        float v = g_tmp[i] + x[i];
        x[i] = v;
        dp += g_rorig[i] * v;
    }
#pragma unroll
    for (int o = 16; o; o >>= 1) dp += __shfl_down_sync(0xffffffffu, dp, o);
    if ((tid & 31) == 0) red[tid >> 5] = dp;
    __syncthreads();
    if (tid == 0) {
        float td = 0.f;
#pragma unroll
        for (int w = 0; w < 16; w++) td += red[w];
        out[0] = g_ld[0] + td;
    }
    for (int i = tid; i < ND; i += 512) g_tmp[i] = x[i];
}

// m_posterior = m0 + P @ x1, via Pt (thread per model row, coalesced)
__global__ __launch_bounds__(256) void kM(float* __restrict__ out,
                                          const float* __restrict__ m0p) {
    __shared__ float sx[ND];
    const int tid = threadIdx.x;
    for (int i = tid; i < ND; i += 256) sx[i] = g_tmp[i];
    __syncthreads();
    const int m = blockIdx.x * 256 + tid;
    if (m >= NM) return;
    float s = 0.f;
#pragma unroll 4
    for (int j = 0; j < ND; j++) s += g_Pt[(size_t)j * NM + m] * sx[j];
    out[1 + m] = m0p[0] + s;
}

// =====================================================================
extern "C" void kernel_launch(void* const* d_in, const int* in_sizes, int n_in,
                              void* d_out, int out_size) {
    const float* D    = (const float*)d_in[0];
    const float* F    = (const float*)d_in[1];
    const float* dobs = (const float*)d_in[2];
    const float* dcov = (const float*)d_in[3];
    const float* m0p  = (const float*)d_in[4];
    const float* lsp  = (const float*)d_in[5];
    const float* sgp  = (const float*)d_in[6];
    float* out = (float*)d_out;

    // host-side objects, created once (not device memory)
    static cudaStream_t s2 = nullptr;
    static cudaEvent_t ev1 = nullptr, ev2 = nullptr;
    if (!s2) {
        cudaStreamCreateWithFlags(&s2, cudaStreamNonBlocking);
        cudaEventCreateWithFlags(&ev1, cudaEventDisableTiming);
        cudaEventCreateWithFlags(&ev2, cudaEventDisableTiming);
    }

    cudaFuncSetAttribute(kLU, cudaFuncAttributeMaxDynamicSharedMemorySize,
                         ND * NB * 4 + ND * 4);
    cudaFuncSetAttribute(kPmma, cudaFuncAttributeMaxDynamicSharedMemorySize, 2 * PSTG);

    kFsplit<<<(ND * NM + 255) / 256, 256>>>(F);
    kInit<<<(ND + 255) / 256, 256>>>();

    // fork: FFMA-pipe branch (kR + kPfma) runs concurrently with HMMA kPmma
    cudaEventRecord(ev1, 0);
    cudaStreamWaitEvent(s2, ev1, 0);
    kR<<<ND, 256, 0, s2>>>(F, dobs, m0p);
    kPfma<<<dim3(9, 79 - MS), 256, 64 * 133 * 4, s2>>>(D, F, lsp, sgp);
    cudaEventRecord(ev2, s2);

    kPmma<<<dim3(MS, 5), 256, 2 * PSTG>>>(D, lsp, sgp);

    // join
    cudaStreamWaitEvent(0, ev2, 0);

    kBmma<<<dim3(5, 5, KSB), 256>>>();
    kC<<<(ND * ND + 255) / 256, 256>>>(dcov);

    for (int p = 0; p < NPANEL; p++) {
        const int p0 = p * NB;
        const int pw = (p == NPANEL - 1) ? (ND - p0) : NB;
        const int nrows = ND - p0;
        kLU<<<1, 512, nrows * pw * 4 + nrows * 4>>>(p0, pw);
        const int m = ND - (p0 + pw);
        const int tcols = ND + 1 - (p0 + pw);
        if (m > 0)
            kG<<<dim3((m + 31) / 32, (tcols + 31) / 32), 256>>>(p0, pw);
    }

    kBack<<<1, 512>>>();
    kAy<<<(NM + 255) / 256, 256>>>(F);
    kAz<<<(NM + 7) / 8, 256>>>(D, lsp, sgp);
    kAw<<<ND, 256>>>(F, dcov);
    kSolve<<<1, 512>>>(out);
    kM<<<(NM + 255) / 256, 256>>>(out, m0p);
}

// round 16
// speedup vs baseline: 1.2205x; 1.2205x over previous
#include <cuda_runtime.h>
#include <cuda_fp16.h>
#include <math.h>
#include <stdint.h>

#define NM 10000
#define ND 552
#define LDA 560          // padded row length of augmented matrix (553 cols used)
#define NB 32
#define NPANEL 18        // 17*32 + 8 = 552
#define KSB 8            // k-split for F @ P
#define NCHUNK 313       // ceil(10000/32)

// ---------------- device scratch (static; no allocation allowed) ----------------
__device__ float   g_Pt[(size_t)ND * NM];           // 22.1 MB  P transposed [j][m]
__device__ __half  g_Fhh[(size_t)ND * NM];          // 11 MB   F fp16 hi
__device__ __half  g_Fhl[(size_t)ND * NM];          // 11 MB   F fp16 lo
__device__ float   g_Bpart[(size_t)KSB * ND * ND];  // 9.8 MB
__device__ float   g_Aaug[(size_t)ND * LDA];        // [A | r] -> LU factors (rows perm'd via g_rp)
__device__ float   g_rorig[ND];
__device__ float   g_tmp[ND];                       // x0 -> x1 -> x2
__device__ int     g_rp[ND];                        // row permutation (logical->physical)
__device__ float   g_ld[1];
__device__ float   g_y[NM];
__device__ float   g_z[NM];
__device__ float   g_resid[ND];

// ===================== helpers ==================
__device__ __forceinline__ uint32_t smem_u32(const void* p) {
    uint32_t a;
    asm("{ .reg .u64 t; cvta.to.shared.u64 t, %1; cvt.u32.u64 %0, t; }" : "=r"(a) : "l"(p));
    return a;
}

__device__ __forceinline__ void ldx4(uint32_t* r, uint32_t addr) {
    asm volatile("ldmatrix.sync.aligned.m8n8.x4.shared.b16 {%0,%1,%2,%3}, [%4];"
                 : "=r"(r[0]), "=r"(r[1]), "=r"(r[2]), "=r"(r[3]) : "r"(addr));
}

// fp16 mma: m16n8k16, f32 accumulate
__device__ __forceinline__ void mma16816h(float* c, const uint32_t* a, uint32_t b0, uint32_t b1) {
    asm volatile(
        "mma.sync.aligned.m16n8k16.row.col.f32.f16.f16.f32 "
        "{%0,%1,%2,%3}, {%4,%5,%6,%7}, {%8,%9}, {%0,%1,%2,%3};"
        : "+f"(c[0]), "+f"(c[1]), "+f"(c[2]), "+f"(c[3])
        : "r"(a[0]), "r"(a[1]), "r"(a[2]), "r"(a[3]), "r"(b0), "r"(b1));
}

__device__ __forceinline__ void split2h(float a, float b, uint32_t& hv, uint32_t& lv) {
    __half ha = __float2half_rn(a), hb = __float2half_rn(b);
    __half2 hh; hh.x = ha; hh.y = hb;
    hv = *(uint32_t*)&hh;
    __half2 ll;
    ll.x = __float2half_rn(a - __half2float(ha));
    ll.y = __float2half_rn(b - __half2float(hb));
    lv = *(uint32_t*)&ll;
}

__device__ __forceinline__ uint32_t pack2h(float a, float b) {
    __half2 hh; hh.x = __float2half_rn(a); hh.y = __float2half_rn(b);
    return *(uint32_t*)&hh;
}

__device__ __forceinline__ void cpasync16(uint32_t dst, const void* src, bool pred) {
    int sz = pred ? 16 : 0;
    asm volatile("cp.async.cg.shared.global [%0], [%1], 16, %2;"
                 :: "r"(dst), "l"(src), "r"(sz) : "memory");
}
#define CP_COMMIT() asm volatile("cp.async.commit_group;" ::: "memory")
#define CP_WAIT1()  asm volatile("cp.async.wait_group 1;" ::: "memory")

// kPmma per-stage layout (bytes): A 0 (10240), Bhi 10240, Blo 20480; stride 30720
#define PSTG2 30720
#define PM_SMEM (2 * PSTG2)   // 61440; epilogue reuses full buffer (needs 34816)

// kBmma static layout (4 arrays of 10240)
#define SM_BYTES 40960
#define A_LO_OFF 10240
#define B_HI_OFF 20480
#define B_LO_OFF 30720

// ============================ F -> fp16 hi/lo split ==========================
__global__ void kFsplit(const float* __restrict__ F) {
    int idx = blockIdx.x * 256 + threadIdx.x;
    if (idx >= ND * NM) return;
    float f = F[idx];
    __half h = __float2half_rn(f);
    g_Fhh[idx] = h;
    g_Fhl[idx] = __float2half_rn(f - __half2float(h));
}

// tiny: init row permutation
__global__ void kInit() {
    int i = blockIdx.x * 256 + threadIdx.x;
    if (i < ND) g_rp[i] = i;
}

// =====================================================================
// kPmma: Pt[j][m] = (s2*exp(c*D)) @ F^T   (fp16, TWO passes: Ah*Bh + Ah*Bl)
// grid (79 m-tiles of 128, 5 j-tiles of 128), 256 threads.
// =====================================================================
__global__ __launch_bounds__(256, 1) void kPmma(const float* __restrict__ Dm,
                                                const float* __restrict__ lsp,
                                                const float* __restrict__ sgp) {
    extern __shared__ __align__(16) char sm[];
    const uint32_t sb = smem_u32(sm);

    const int tid = threadIdx.x, lane = tid & 31, wid = tid >> 5;
    const int m0 = blockIdx.x * 128, j0 = blockIdx.y * 128;

    const float l = lsp[0];
    const float cexp = -0.5f / (l * l);
    const float s2 = sgp[0] * sgp[0];

    const int lr = tid >> 1, lk = (tid & 1) * 16;
    const bool mval = (m0 + lr) < NM;
    const bool nval = (j0 + lr) < ND;
    const int jrow = nval ? (j0 + lr) : (ND - 1);
    const float* Dp = Dm + (size_t)(m0 + lr) * NM + lk;
    const __half* Fh = g_Fhh + (size_t)jrow * NM + lk;
    const __half* Fl = g_Fhl + (size_t)jrow * NM + lk;

    const uint32_t sA = (uint32_t)(lr * 40 + lk) * 2;   // byte offset within array

    float4 dv[4];
    bool dok[4];

#define LOADD(ch)                                                             \
    {                                                                         \
        int _k0 = (ch) * 32;                                                  \
        _Pragma("unroll")                                                     \
        for (int i = 0; i < 4; i++) {                                         \
            int kk = _k0 + lk + i * 4;                                        \
            dok[i] = mval && (kk < NM);                                       \
            dv[i] = dok[i] ? *(const float4*)(Dp + _k0 + i * 4)               \
                           : make_float4(0.f, 0.f, 0.f, 0.f);                 \
        }                                                                     \
    }

#define ISSUEF(ch, s)                                                         \
    {                                                                         \
        int _k0 = (ch) * 32;                                                  \
        bool ok  = nval && (_k0 + lk < NM);                                   \
        bool ok2 = nval && (_k0 + lk + 8 < NM);                               \
        uint32_t dB = sb + (s) * PSTG2 + 10240 + sA;                          \
        cpasync16(dB,              Fh + _k0,     ok);                         \
        cpasync16(dB + 16,         Fh + _k0 + 8, ok2);                        \
        cpasync16(dB + 10240,      Fl + _k0,     ok);                         \
        cpasync16(dB + 10240 + 16, Fl + _k0 + 8, ok2);                        \
    }

#define STSA(s)                                                               \
    {                                                                         \
        char* stg = sm + (s) * PSTG2;                                         \
        _Pragma("unroll")                                                     \
        for (int i = 0; i < 4; i++) {                                         \
            float e0 = dok[i] ? s2 * __expf(cexp * dv[i].x) : 0.f;            \
            float e1 = dok[i] ? s2 * __expf(cexp * dv[i].y) : 0.f;            \
            float e2 = dok[i] ? s2 * __expf(cexp * dv[i].z) : 0.f;            \
            float e3 = dok[i] ? s2 * __expf(cexp * dv[i].w) : 0.f;            \
            uint32_t h01 = pack2h(e0, e1);                                    \
            uint32_t h23 = pack2h(e2, e3);                                    \
            *(uint2*)(stg + sA + i * 8) = make_uint2(h01, h23);               \
        }                                                                     \
    }

    const int wm = (wid & 3) * 32, wn = (wid >> 2) * 64;
    const uint32_t aAoff = (uint32_t)((wm + (lane & 15)) * 40 + ((lane >> 4) & 1) * 8) * 2;
    const uint32_t aBoff = (uint32_t)((wn + ((lane >> 4) << 3) + (lane & 7)) * 40
                                      + ((lane >> 3) & 1) * 8) * 2;

    float acc[2][8][4];
#pragma unroll
    for (int a = 0; a < 2; a++)
#pragma unroll
        for (int b = 0; b < 8; b++)
#pragma unroll
            for (int d = 0; d < 4; d++) acc[a][b][d] = 0.f;

    LOADD(0);
    ISSUEF(0, 0); CP_COMMIT();
    STSA(0);
    LOADD(1);
    ISSUEF(1, 1); CP_COMMIT();
    CP_WAIT1();
    __syncthreads();

    for (int ch = 0; ch < NCHUNK; ++ch) {
        const int s = ch & 1;
        const uint32_t base = sb + s * PSTG2;

#pragma unroll
        for (int kst = 0; kst < 2; ++kst) {
            uint32_t ah[2][4];
#pragma unroll
            for (int mt = 0; mt < 2; ++mt) {
                uint32_t o = aAoff + mt * 1280 + kst * 32;
                ldx4(ah[mt], base + o);
            }
#pragma unroll
            for (int nh = 0; nh < 2; ++nh) {
                uint32_t bh[2][4], bl[2][4];
#pragma unroll
                for (int ng = 0; ng < 2; ++ng) {
                    uint32_t o = aBoff + nh * 2560 + ng * 1280 + kst * 32;
                    ldx4(bh[ng], base + 10240 + o);
                    ldx4(bl[ng], base + 20480 + o);
                }
#pragma unroll
                for (int mt = 0; mt < 2; mt++)
#pragma unroll
                    for (int nt = 0; nt < 4; nt++) {
                        float* cc = acc[mt][nh * 4 + nt];
                        uint32_t b0h = bh[nt >> 1][(nt & 1) * 2];
                        uint32_t b1h = bh[nt >> 1][(nt & 1) * 2 + 1];
                        uint32_t b0l = bl[nt >> 1][(nt & 1) * 2];
                        uint32_t b1l = bl[nt >> 1][(nt & 1) * 2 + 1];
                        mma16816h(cc, ah[mt], b0h, b1h);
                        mma16816h(cc, ah[mt], b0l, b1l);
                    }
            }
        }
        __syncthreads();

        if (ch + 2 < NCHUNK) ISSUEF(ch + 2, s);
        CP_COMMIT();
        if (ch + 1 < NCHUNK) STSA(s ^ 1);
        if (ch + 2 < NCHUNK) LOADD(ch + 2);
        CP_WAIT1();
        __syncthreads();
    }

    // epilogue: transpose via smem staging (reuses full 61440B buffer)
    float* stg = (float*)sm;  // [128 n][68 m] per 64-m half = 34816 B
#pragma unroll
    for (int h = 0; h < 2; ++h) {
        __syncthreads();
        if (((wid & 3) >> 1) == h) {
            const int rb = wm - h * 64 + (lane >> 2);
            const int cb = 2 * (lane & 3);
#pragma unroll
            for (int mt = 0; mt < 2; mt++)
#pragma unroll
                for (int nt = 0; nt < 8; nt++) {
                    int r = rb + mt * 16;
                    int c = wn + ((nt >> 2) * 32) + ((nt & 3) * 8) + cb;
                    stg[(c + 0) * 68 + r]     = acc[mt][nt][0];
                    stg[(c + 1) * 68 + r]     = acc[mt][nt][1];
                    stg[(c + 0) * 68 + r + 8] = acc[mt][nt][2];
                    stg[(c + 1) * 68 + r + 8] = acc[mt][nt][3];
                }
        }
        __syncthreads();
#pragma unroll 4
        for (int it = 0; it < 32; ++it) {
            int nr = it * 4 + (tid >> 6);
            int mc = tid & 63;
            int j = j0 + nr, m = m0 + h * 64 + mc;
            if (j < ND && m < NM) g_Pt[(size_t)j * NM + m] = stg[nr * 68 + mc];
        }
    }
}

// =====================================================================
// kBmma: Bpart[z] = F @ P   (fp16 3-pass: hh + hl + lh; error ~2^-22)
// =====================================================================
__global__ __launch_bounds__(256, 1) void kBmma() {
    __shared__ __align__(16) char sm[SM_BYTES];
    __half* Ahi = (__half*)sm;
    __half* Alo = (__half*)(sm + A_LO_OFF);
    __half* Bhi = (__half*)(sm + B_HI_OFF);
    __half* Blo = (__half*)(sm + B_LO_OFF);
    const uint32_t sb = smem_u32(sm);

    const int tid = threadIdx.x, lane = tid & 31, wid = tid >> 5;
    const int i0 = blockIdx.x * 128, j0 = blockIdx.y * 128;
    const int z = blockIdx.z;
    const int c0 = z * 40;
    const int c1 = min(NCHUNK, c0 + 40);

    const int lr = tid >> 1, lk = (tid & 1) * 16;
    const bool ival = (i0 + lr) < ND;
    const bool jval = (j0 + lr) < ND;
    const __half* Fh = g_Fhh + (size_t)(i0 + lr) * NM + lk;
    const __half* Fl = g_Fhl + (size_t)(i0 + lr) * NM + lk;
    const float* Pp = g_Pt + (size_t)(j0 + lr) * NM + lk;

    float4 pv[4];
    bool pok[4];
    uint4 fh[2], fl[2];

#define LOADCH_B(k0)                                                          \
    {                                                                         \
        _Pragma("unroll")                                                     \
        for (int i = 0; i < 2; i++) {                                         \
            int kk = (k0) + lk + i * 8;                                       \
            bool ok = ival && (kk < NM);                                      \
            fh[i] = ok ? *(const uint4*)(Fh + (k0) + i * 8) : make_uint4(0, 0, 0, 0); \
            fl[i] = ok ? *(const uint4*)(Fl + (k0) + i * 8) : make_uint4(0, 0, 0, 0); \
        }                                                                     \
        _Pragma("unroll")                                                     \
        for (int i = 0; i < 4; i++) {                                         \
            int kk = (k0) + lk + i * 4;                                       \
            pok[i] = jval && (kk < NM);                                       \
            pv[i] = pok[i] ? *(const float4*)(Pp + (k0) + i * 4)              \
                           : make_float4(0.f, 0.f, 0.f, 0.f);                 \
        }                                                                     \
    }

    const int sA = lr * 40 + lk;
    const int wm = (wid & 3) * 32, wn = (wid >> 2) * 64;
    const uint32_t aAoff = (uint32_t)((wm + (lane & 15)) * 40 + ((lane >> 4) & 1) * 8) * 2;
    const uint32_t aBoff = (uint32_t)((wn + ((lane >> 4) << 3) + (lane & 7)) * 40
                                      + ((lane >> 3) & 1) * 8) * 2;

    float acc[2][8][4];
#pragma unroll
    for (int a = 0; a < 2; a++)
#pragma unroll
        for (int b = 0; b < 8; b++)
#pragma unroll
            for (int d = 0; d < 4; d++) acc[a][b][d] = 0.f;

    LOADCH_B(c0 * 32);

    for (int ch = c0; ch < c1; ++ch) {
        *(uint4*)(Ahi + sA) = fh[0];
        *(uint4*)(Ahi + sA + 8) = fh[1];
        *(uint4*)(Alo + sA) = fl[0];
        *(uint4*)(Alo + sA + 8) = fl[1];
#pragma unroll
        for (int i = 0; i < 4; i++) {
            uint32_t h01, l01, h23, l23;
            split2h(pv[i].x, pv[i].y, h01, l01);
            split2h(pv[i].z, pv[i].w, h23, l23);
            *(uint2*)(Bhi + sA + i * 4) = make_uint2(h01, h23);
            *(uint2*)(Blo + sA + i * 4) = make_uint2(l01, l23);
        }
        __syncthreads();

        if (ch + 1 < c1) LOADCH_B((ch + 1) * 32);

#pragma unroll
        for (int kst = 0; kst < 2; ++kst) {
            uint32_t ah[2][4], al[2][4];
#pragma unroll
            for (int mt = 0; mt < 2; ++mt) {
                uint32_t o = aAoff + mt * 1280 + kst * 32;
                ldx4(ah[mt], sb + o);
                ldx4(al[mt], sb + A_LO_OFF + o);
            }
#pragma unroll
            for (int nh = 0; nh < 2; ++nh) {
                uint32_t bh[2][4], bl[2][4];
#pragma unroll
                for (int ng = 0; ng < 2; ++ng) {
                    uint32_t o = aBoff + nh * 2560 + ng * 1280 + kst * 32;
                    ldx4(bh[ng], sb + B_HI_OFF + o);
                    ldx4(bl[ng], sb + B_LO_OFF + o);
                }
#pragma unroll
                for (int mt = 0; mt < 2; mt++)
#pragma unroll
                    for (int nt = 0; nt < 4; nt++) {
                        float* cc = acc[mt][nh * 4 + nt];
                        uint32_t b0h = bh[nt >> 1][(nt & 1) * 2];
                        uint32_t b1h = bh[nt >> 1][(nt & 1) * 2 + 1];
                        uint32_t b0l = bl[nt >> 1][(nt & 1) * 2];
                        uint32_t b1l = bl[nt >> 1][(nt & 1) * 2 + 1];
                        mma16816h(cc, ah[mt], b0h, b1h);
                        mma16816h(cc, ah[mt], b0l, b1l);
                        mma16816h(cc, al[mt], b0h, b1h);
                    }
            }
        }
        __syncthreads();
    }

    float* Bp = g_Bpart + (size_t)z * ND * ND;
    const int rb = i0 + wm + (lane >> 2);
    const int cb = j0 + wn + 2 * (lane & 3);
#pragma unroll
    for (int mt = 0; mt < 2; mt++)
#pragma unroll
        for (int nt = 0; nt < 8; nt++) {
            int i = rb + mt * 16;
            int c = cb + (nt >> 2) * 32 + (nt & 3) * 8;
            if (c < ND) {
                if (i < ND)
                    *(float2*)(Bp + (size_t)i * ND + c) = make_float2(acc[mt][nt][0], acc[mt][nt][1]);
                if (i + 8 < ND)
                    *(float2*)(Bp + (size_t)(i + 8) * ND + c) = make_float2(acc[mt][nt][2], acc[mt][nt][3]);
            }
        }
}

// combine k-split partials + data_cov into Aaug
__global__ void kC(const float* __restrict__ dcov) {
    int idx = blockIdx.x * 256 + threadIdx.x;
    if (idx >= ND * ND) return;
    float s = dcov[idx];
#pragma unroll
    for (int zz = 0; zz < KSB; zz++) s += g_Bpart[(size_t)zz * ND * ND + idx];
    int i = idx / ND, j = idx - i * ND;
    g_Aaug[i * LDA + j] = s;
}

// prior misfit r = d_obs - m0 * rowsum(F)
__global__ __launch_bounds__(256) void kR(const float* __restrict__ F,
                                          const float* __restrict__ dobs,
                                          const float* __restrict__ m0p) {
    __shared__ float red[8];
    const int i = blockIdx.x;
    const float* row = F + (size_t)i * NM;
    float s = 0.f;
    for (int t = threadIdx.x; t < NM; t += 256) s += row[t];
#pragma unroll
    for (int o = 16; o; o >>= 1) s += __shfl_down_sync(0xffffffffu, s, o);
    if ((threadIdx.x & 31) == 0) red[threadIdx.x >> 5] = s;
    __syncthreads();
    if (threadIdx.x == 0) {
        float tot = 0.f;
#pragma unroll
        for (int w = 0; w < 8; w++) tot += red[w];
        float r = dobs[i] - m0p[0] * tot;
        g_Aaug[i * LDA + ND] = r;
        g_rorig[i] = r;
    }
}

// =====================================================================
// kLU: panel factor (perm-vector pivoting) + fused TRSM (padded Ls)
// =====================================================================
__global__ __launch_bounds__(512) void kLU(int p0, int pw) {
    extern __shared__ float dyn[];
    const int tid = threadIdx.x, lane = tid & 31, wid = tid >> 5;
    const int nrows = ND - p0;
    float* sp  = dyn;
    int*   srp = (int*)(dyn + nrows * pw);

    __shared__ float s_pv;
    __shared__ float Ls[32][33];

    for (int i = tid; i < nrows; i += 512) srp[i] = g_rp[p0 + i];
    __syncthreads();
    for (int idx = tid; idx < nrows * pw; idx += 512)
        sp[idx] = g_Aaug[(size_t)srp[idx / pw] * LDA + p0 + (idx % pw)];

    for (int j = 0; j < pw; j++) {
        __syncthreads();
        if (wid == 0) {
            float best = -1.f; int bi = j;
            for (int i = j + lane; i < nrows; i += 32) {
                float v = fabsf(sp[i * pw + j]);
                if (v > best) { best = v; bi = i; }
            }
#pragma unroll
            for (int o = 16; o; o >>= 1) {
                float ov = __shfl_down_sync(0xffffffffu, best, o);
                int   oi = __shfl_down_sync(0xffffffffu, bi,   o);
                if (ov > best) { best = ov; bi = oi; }
            }
            int piv = __shfl_sync(0xffffffffu, bi, 0);
            if (piv != j) {
                if (lane < pw) {
                    float t = sp[j * pw + lane];
                    sp[j * pw + lane] = sp[piv * pw + lane];
                    sp[piv * pw + lane] = t;
                }
                if (lane == 0) { int t = srp[j]; srp[j] = srp[piv]; srp[piv] = t; }
            }
            __syncwarp();
            if (lane == 0) s_pv = sp[j * pw + j];
        }
        __syncthreads();
        const float inv = 1.f / s_pv;
        for (int i = j + 1 + tid; i < nrows; i += 512) {
            float lij = sp[i * pw + j] * inv;
            sp[i * pw + j] = lij;
            for (int jj = j + 1; jj < pw; jj++)
                sp[i * pw + jj] -= lij * sp[j * pw + jj];
        }
    }
    __syncthreads();

    for (int idx = tid; idx < 32 * 33; idx += 512) ((float*)Ls)[idx] = 0.f;
    __syncthreads();
    for (int idx = tid; idx < nrows * pw; idx += 512)
        g_Aaug[(size_t)srp[idx / pw] * LDA + p0 + (idx % pw)] = sp[idx];
    for (int i = tid; i < nrows; i += 512) g_rp[p0 + i] = srp[i];
    for (int idx = tid; idx < pw * pw; idx += 512)
        Ls[idx / pw][idx % pw] = sp[(idx / pw) * pw + (idx % pw)];
    __syncthreads();

    for (int c = p0 + pw + tid; c <= ND; c += 512) {
        float v[32];
#pragma unroll
        for (int i = 0; i < 32; i++)
            v[i] = (i < pw) ? g_Aaug[(size_t)srp[i] * LDA + c] : 0.f;
#pragma unroll
        for (int k = 0; k < 32; k++) {
            if (k >= pw) break;
            float vk = v[k];
#pragma unroll
            for (int i = 0; i < 32; i++)
                if (i > k) v[i] -= Ls[i][k] * vk;
        }
#pragma unroll
        for (int i = 0; i < 32; i++)
            if (i < pw) g_Aaug[(size_t)srp[i] * LDA + c] = v[i];
    }
}

// A22 -= L21 @ U12  (rows via g_rp)
__global__ __launch_bounds__(256) void kG(int p0, int pw) {
    __shared__ float Ls[32][33];
    __shared__ float Us[32][36];
    __shared__ int   rmap[32];
    const int tid = threadIdx.x;
    const int r0  = p0 + pw;
    const int gi0 = r0 + blockIdx.x * 32;
    const int gj0 = r0 + blockIdx.y * 32;

    if (tid < 32) rmap[tid] = (gi0 + tid < ND) ? g_rp[gi0 + tid] : 0;
    __syncthreads();

    for (int idx = tid; idx < 32 * 32; idx += 256) {
        int i = idx >> 5, k = idx & 31;
        float v = 0.f;
        if (k < pw && gi0 + i < ND) v = g_Aaug[(size_t)rmap[i] * LDA + p0 + k];
        Ls[i][k] = v;
    }
    for (int idx = tid; idx < 32 * 32; idx += 256) {
        int k = idx >> 5, jn = idx & 31;
        float v = 0.f;
        if (k < pw && gj0 + jn <= ND) v = g_Aaug[(size_t)g_rp[p0 + k] * LDA + gj0 + jn];
        Us[k][jn] = v;
    }
    __syncthreads();

    const int mi = tid >> 3;
    const int nj = (tid & 7) * 4;
    float a0 = 0.f, a1 = 0.f, a2 = 0.f, a3 = 0.f;
    for (int k = 0; k < pw; k++) {
        float a = Ls[mi][k];
        a0 += a * Us[k][nj + 0];
        a1 += a * Us[k][nj + 1];
        a2 += a * Us[k][nj + 2];
        a3 += a * Us[k][nj + 3];
    }
    const int gi = gi0 + mi;
    if (gi < ND) {
        float* rowp = g_Aaug + (size_t)rmap[mi] * LDA;
        if (gj0 + nj + 0 <= ND) rowp[gj0 + nj + 0] -= a0;
        if (gj0 + nj + 1 <= ND) rowp[gj0 + nj + 1] -= a1;
        if (gj0 + nj + 2 <= ND) rowp[gj0 + nj + 2] -= a2;
        if (gj0 + nj + 3 <= ND) rowp[gj0 + nj + 3] -= a3;
    }
}

// back-substitution (warp-shuffle diag blocks) -> x0; logdet -> g_ld
__global__ __launch_bounds__(512) void kBack(void) {
    __shared__ float x[ND];
    __shared__ float ub[32][33];
    __shared__ float red[16];
    const int tid = threadIdx.x;

    for (int i = tid; i < ND; i += 512) x[i] = g_Aaug[(size_t)g_rp[i] * LDA + ND];
    float ld = 0.f;
    for (int k = tid; k < ND; k += 512) ld += logf(fabsf(g_Aaug[(size_t)g_rp[k] * LDA + k]));
    __syncthreads();

    for (int pb = NPANEL - 1; pb >= 0; pb--) {
        const int p0 = pb * NB;
        const int pw = (pb == NPANEL - 1) ? (ND - p0) : NB;
        for (int idx = tid; idx < pw * pw; idx += 512)
            ub[idx / pw][idx % pw] = g_Aaug[(size_t)g_rp[p0 + idx / pw] * LDA + p0 + (idx % pw)];
        __syncthreads();
        if (tid < 32) {
            float xi = (tid < pw) ? x[p0 + tid] : 0.f;
            for (int j = pw - 1; j >= 0; j--) {
                if (tid == j) xi /= ub[j][j];
                float xj = __shfl_sync(0xffffffffu, xi, j);
                if (tid < j) xi -= ub[tid][j] * xj;
            }
            if (tid < pw) x[p0 + tid] = xi;
        }
        __syncthreads();
        for (int i = tid; i < p0; i += 512) {
            float s = 0.f;
            for (int j = 0; j < pw; j++)
                s += g_Aaug[(size_t)g_rp[i] * LDA + p0 + j] * x[p0 + j];
            x[i] -= s;
        }
        __syncthreads();
    }

#pragma unroll
    for (int o = 16; o; o >>= 1) ld += __shfl_down_sync(0xffffffffu, ld, o);
    if ((tid & 31) == 0) red[tid >> 5] = ld;
    __syncthreads();
    if (tid == 0) {
        float tl = 0.f;
        for (int w = 0; w < 16; w++) tl += red[w];
        g_ld[0] = tl;
    }
    for (int i = tid; i < ND; i += 512) g_tmp[i] = x[i];
}

// ===================== iterative refinement: exact fp32 operator =============
__global__ __launch_bounds__(256) void kAy(const float* __restrict__ F) {
    __shared__ float sx[ND];
    const int tid = threadIdx.x;
    for (int i = tid; i < ND; i += 256) sx[i] = g_tmp[i];
    __syncthreads();
    const int m = blockIdx.x * 256 + tid;
    if (m >= NM) return;
    float s = 0.f;
#pragma unroll 4
    for (int i = 0; i < ND; i++) s += F[(size_t)i * NM + m] * sx[i];
    g_y[m] = s;
}

__global__ __launch_bounds__(256) void kAz(const float* __restrict__ Dm,
                                           const float* __restrict__ lsp,
                                           const float* __restrict__ sgp) {
    const int tid = threadIdx.x, lane = tid & 31, warp = tid >> 5;
    const int row = blockIdx.x * 8 + warp;
    if (row >= NM) return;
    const float l = lsp[0];
    const float c = -0.5f / (l * l);
    const float s2 = sgp[0] * sgp[0];
    const float* dr = Dm + (size_t)row * NM;
    float s = 0.f;
    for (int k = lane; k < NM; k += 32) s += __expf(c * dr[k]) * __ldg(&g_y[k]);
#pragma unroll
    for (int o = 16; o; o >>= 1) s += __shfl_down_sync(0xffffffffu, s, o);
    if (lane == 0) g_z[row] = s2 * s;
}

__global__ __launch_bounds__(256) void kAw(const float* __restrict__ F,
                                           const float* __restrict__ dcov) {
    __shared__ float red[8];
    const int i = blockIdx.x;
    const int tid = threadIdx.x;
    float s = 0.f;
    const float* fr = F + (size_t)i * NM;
    for (int m = tid; m < NM; m += 256) s += fr[m] * g_z[m];
    const float* cr = dcov + (size_t)i * ND;
    for (int j = tid; j < ND; j += 256) s += cr[j] * g_tmp[j];
#pragma unroll
    for (int o = 16; o; o >>= 1) s += __shfl_down_sync(0xffffffffu, s, o);
    if ((tid & 31) == 0) red[tid >> 5] = s;
    __syncthreads();
    if (tid == 0) {
        float tot = 0.f;
#pragma unroll
        for (int w = 0; w < 8; w++) tot += red[w];
        g_resid[i] = g_rorig[i] - tot;
    }
}

// solve LU dx = P resid; x += dx; out[0] = logdet + r^T x; g_tmp = x
__global__ __launch_bounds__(512) void kSolve(float* __restrict__ out) {
    __shared__ float x[ND];
    __shared__ float Bs[32][33];
    __shared__ float red[16];
    const int tid = threadIdx.x;

    for (int i = tid; i < ND; i += 512) x[i] = g_resid[g_rp[i]];
    __syncthreads();

    for (int pb = 0; pb < NPANEL; pb++) {
        const int p0 = pb * NB;
        const int pw = (pb == NPANEL - 1) ? (ND - p0) : NB;
        for (int idx = tid; idx < pw * pw; idx += 512)
            Bs[idx / pw][idx % pw] = g_Aaug[(size_t)g_rp[p0 + idx / pw] * LDA + p0 + (idx % pw)];
        __syncthreads();
        if (tid < 32) {
            float xi = (tid < pw) ? x[p0 + tid] : 0.f;
            for (int j = 0; j < pw; j++) {
                float xj = __shfl_sync(0xffffffffu, xi, j);
                if (tid > j && tid < pw) xi -= Bs[tid][j] * xj;
            }
            if (tid < pw) x[p0 + tid] = xi;
        }
        __syncthreads();
        for (int i = p0 + pw + tid; i < ND; i += 512) {
            float s = 0.f;
            for (int j = 0; j < pw; j++)
                s += g_Aaug[(size_t)g_rp[i] * LDA + p0 + j] * x[p0 + j];
            x[i] -= s;
        }
        __syncthreads();
    }

    for (int pb = NPANEL - 1; pb >= 0; pb--) {
        const int p0 = pb * NB;
        const int pw = (pb == NPANEL - 1) ? (ND - p0) : NB;
        for (int idx = tid; idx < pw * pw; idx += 512)
            Bs[idx / pw][idx % pw] = g_Aaug[(size_t)g_rp[p0 + idx / pw] * LDA + p0 + (idx % pw)];
        __syncthreads();
        if (tid < 32) {
            float xi = (tid < pw) ? x[p0 + tid] : 0.f;
            for (int j = pw - 1; j >= 0; j--) {
                if (tid == j) xi /= Bs[j][j];
                float xj = __shfl_sync(0xffffffffu, xi, j);
                if (tid < j) xi -= Bs[tid][j] * xj;
            }
            if (tid < pw) x[p0 + tid] = xi;
        }
        __syncthreads();
        for (int i = tid; i < p0; i += 512) {
            float s = 0.f;
            for (int j = 0; j < pw; j++)
                s += g_Aaug[(size_t)g_rp[i] * LDA + p0 + j] * x[p0 + j];
            x[i] -= s;
        }
        __syncthreads();
    }

    float dp = 0.f;
    for (int i = tid; i < ND; i += 512) {
        float v = g_tmp[i] + x[i];
        x[i] = v;
        dp += g_rorig[i] * v;
    }
#pragma unroll
    for (int o = 16; o; o >>= 1) dp += __shfl_down_sync(0xffffffffu, dp, o);
    if ((tid & 31) == 0) red[tid >> 5] = dp;
    __syncthreads();
    if (tid == 0) {
        float td = 0.f;
#pragma unroll
        for (int w = 0; w < 16; w++) td += red[w];
        out[0] = g_ld[0] + td;
    }
    for (int i = tid; i < ND; i += 512) g_tmp[i] = x[i];
}

// m_posterior = m0 + P @ x, via Pt (thread per model row, coalesced)
__global__ __launch_bounds__(256) void kM(float* __restrict__ out,
                                          const float* __restrict__ m0p) {
    __shared__ float sx[ND];
    const int tid = threadIdx.x;
    for (int i = tid; i < ND; i += 256) sx[i] = g_tmp[i];
    __syncthreads();
    const int m = blockIdx.x * 256 + tid;
    if (m >= NM) return;
    float s = 0.f;
#pragma unroll 4
    for (int j = 0; j < ND; j++) s += g_Pt[(size_t)j * NM + m] * sx[j];
    out[1 + m] = m0p[0] + s;
}

// =====================================================================
extern "C" void kernel_launch(void* const* d_in, const int* in_sizes, int n_in,
                              void* d_out, int out_size) {
    const float* D    = (const float*)d_in[0];
    const float* F    = (const float*)d_in[1];
    const float* dobs = (const float*)d_in[2];
    const float* dcov = (const float*)d_in[3];
    const float* m0p  = (const float*)d_in[4];
    const float* lsp  = (const float*)d_in[5];
    const float* sgp  = (const float*)d_in[6];
    float* out = (float*)d_out;

    cudaFuncSetAttribute(kLU, cudaFuncAttributeMaxDynamicSharedMemorySize,
                         ND * NB * 4 + ND * 4);
    cudaFuncSetAttribute(kPmma, cudaFuncAttributeMaxDynamicSharedMemorySize, PM_SMEM);

    // kPmma is launch #4 -> ncu capture lands on it
    kFsplit<<<(ND * NM + 255) / 256, 256>>>(F);
    kR<<<ND, 256>>>(F, dobs, m0p);
    kInit<<<(ND + 255) / 256, 256>>>();
    kPmma<<<dim3(79, 5), 256, PM_SMEM>>>(D, lsp, sgp);
    kBmma<<<dim3(5, 5, KSB), 256>>>();
    kC<<<(ND * ND + 255) / 256, 256>>>(dcov);

    for (int p = 0; p < NPANEL; p++) {
        const int p0 = p * NB;
        const int pw = (p == NPANEL - 1) ? (ND - p0) : NB;
        const int nrows = ND - p0;
        kLU<<<1, 512, nrows * pw * 4 + nrows * 4>>>(p0, pw);
        const int m = ND - (p0 + pw);
        const int tcols = ND + 1 - (p0 + pw);
        if (m > 0)
            kG<<<dim3((m + 31) / 32, (tcols + 31) / 32), 256>>>(p0, pw);
    }

    kBack<<<1, 512>>>();

    // TWO refinement iterations (operator error ~3e-4 from fp16 2-pass P)
    for (int it = 0; it < 2; ++it) {
        kAy<<<(NM + 255) / 256, 256>>>(F);
        kAz<<<(NM + 7) / 8, 256>>>(D, lsp, sgp);
        kAw<<<ND, 256>>>(F, dcov);
        kSolve<<<1, 512>>>(out);
    }

    kM<<<(NM + 255) / 256, 256>>>(out, m0p);
}

// round 17
// speedup vs baseline: 2.1642x; 1.7732x over previous
#include <cuda_runtime.h>
#include <cuda_fp16.h>
#include <math.h>
#include <stdint.h>

#define NM 10000
#define ND 552
#define LDA 560          // padded row length of augmented matrix (553 cols used)
#define NB 32
#define PWP 33           // padded smem panel row stride (bank-conflict-free)
#define NPANEL 18        // 17*32 + 8 = 552
#define KSB 8            // k-split for F @ P
#define NCHUNK 313       // ceil(10000/32)

// ---------------- device scratch (static; no allocation allowed) ----------------
__device__ float   g_Pt[(size_t)ND * NM];           // 22.1 MB  P transposed [j][m]
__device__ __half  g_Fhh[(size_t)ND * NM];          // 11 MB   F fp16 hi
__device__ __half  g_Fhl[(size_t)ND * NM];          // 11 MB   F fp16 lo
__device__ float   g_Bpart[(size_t)KSB * ND * ND];  // 9.8 MB
__device__ float   g_Aaug[(size_t)ND * LDA];        // [A | r] -> LU factors (rows perm'd via g_rp)
__device__ float   g_rorig[ND];
__device__ float   g_tmp[ND];                       // x0 -> x1 -> x2
__device__ int     g_rp[ND];                        // row permutation (logical->physical)
__device__ float   g_ld[1];
__device__ float   g_y[NM];
__device__ float   g_z[NM];
__device__ float   g_resid[ND];

// ===================== helpers ==================
__device__ __forceinline__ uint32_t smem_u32(const void* p) {
    uint32_t a;
    asm("{ .reg .u64 t; cvta.to.shared.u64 t, %1; cvt.u32.u64 %0, t; }" : "=r"(a) : "l"(p));
    return a;
}

__device__ __forceinline__ void ldx4(uint32_t* r, uint32_t addr) {
    asm volatile("ldmatrix.sync.aligned.m8n8.x4.shared.b16 {%0,%1,%2,%3}, [%4];"
                 : "=r"(r[0]), "=r"(r[1]), "=r"(r[2]), "=r"(r[3]) : "r"(addr));
}

// fp16 mma: m16n8k16, f32 accumulate
__device__ __forceinline__ void mma16816h(float* c, const uint32_t* a, uint32_t b0, uint32_t b1) {
    asm volatile(
        "mma.sync.aligned.m16n8k16.row.col.f32.f16.f16.f32 "
        "{%0,%1,%2,%3}, {%4,%5,%6,%7}, {%8,%9}, {%0,%1,%2,%3};"
        : "+f"(c[0]), "+f"(c[1]), "+f"(c[2]), "+f"(c[3])
        : "r"(a[0]), "r"(a[1]), "r"(a[2]), "r"(a[3]), "r"(b0), "r"(b1));
}

__device__ __forceinline__ void split2h(float a, float b, uint32_t& hv, uint32_t& lv) {
    __half ha = __float2half_rn(a), hb = __float2half_rn(b);
    __half2 hh; hh.x = ha; hh.y = hb;
    hv = *(uint32_t*)&hh;
    __half2 ll;
    ll.x = __float2half_rn(a - __half2float(ha));
    ll.y = __float2half_rn(b - __half2float(hb));
    lv = *(uint32_t*)&ll;
}

__device__ __forceinline__ uint32_t pack2h(float a, float b) {
    __half2 hh; hh.x = __float2half_rn(a); hh.y = __float2half_rn(b);
    return *(uint32_t*)&hh;
}

__device__ __forceinline__ void cpasync16(uint32_t dst, const void* src, bool pred) {
    int sz = pred ? 16 : 0;
    asm volatile("cp.async.cg.shared.global [%0], [%1], 16, %2;"
                 :: "r"(dst), "l"(src), "r"(sz) : "memory");
}
#define CP_COMMIT() asm volatile("cp.async.commit_group;" ::: "memory")
#define CP_WAIT1()  asm volatile("cp.async.wait_group 1;" ::: "memory")

// kPmma per-stage layout (bytes): A 0 (10240), Bhi 10240, Blo 20480; stride 30720
#define PSTG2 30720
#define PM_SMEM (2 * PSTG2)   // 61440; epilogue reuses full buffer (needs 34816)

// kBmma static layout (4 arrays of 10240)
#define SM_BYTES 40960
#define A_LO_OFF 10240
#define B_HI_OFF 20480
#define B_LO_OFF 30720

// ============================ F -> fp16 hi/lo split ==========================
__global__ void kFsplit(const float* __restrict__ F) {
    int idx = blockIdx.x * 256 + threadIdx.x;
    if (idx >= ND * NM) return;
    float f = F[idx];
    __half h = __float2half_rn(f);
    g_Fhh[idx] = h;
    g_Fhl[idx] = __float2half_rn(f - __half2float(h));
}

// tiny: init row permutation
__global__ void kInit() {
    int i = blockIdx.x * 256 + threadIdx.x;
    if (i < ND) g_rp[i] = i;
}

// =====================================================================
// kPmma: Pt[j][m] = (s2*exp(c*D)) @ F^T   (fp16, TWO passes: Ah*Bh + Ah*Bl)
// =====================================================================
__global__ __launch_bounds__(256, 1) void kPmma(const float* __restrict__ Dm,
                                                const float* __restrict__ lsp,
                                                const float* __restrict__ sgp) {
    extern __shared__ __align__(16) char sm[];
    const uint32_t sb = smem_u32(sm);

    const int tid = threadIdx.x, lane = tid & 31, wid = tid >> 5;
    const int m0 = blockIdx.x * 128, j0 = blockIdx.y * 128;

    const float l = lsp[0];
    const float cexp = -0.5f / (l * l);
    const float s2 = sgp[0] * sgp[0];

    const int lr = tid >> 1, lk = (tid & 1) * 16;
    const bool mval = (m0 + lr) < NM;
    const bool nval = (j0 + lr) < ND;
    const int jrow = nval ? (j0 + lr) : (ND - 1);
    const float* Dp = Dm + (size_t)(m0 + lr) * NM + lk;
    const __half* Fh = g_Fhh + (size_t)jrow * NM + lk;
    const __half* Fl = g_Fhl + (size_t)jrow * NM + lk;

    const uint32_t sA = (uint32_t)(lr * 40 + lk) * 2;   // byte offset within array

    float4 dv[4];
    bool dok[4];

#define LOADD(ch)                                                             \
    {                                                                         \
        int _k0 = (ch) * 32;                                                  \
        _Pragma("unroll")                                                     \
        for (int i = 0; i < 4; i++) {                                         \
            int kk = _k0 + lk + i * 4;                                        \
            dok[i] = mval && (kk < NM);                                       \
            dv[i] = dok[i] ? *(const float4*)(Dp + _k0 + i * 4)               \
                           : make_float4(0.f, 0.f, 0.f, 0.f);                 \
        }                                                                     \
    }

#define ISSUEF(ch, s)                                                         \
    {                                                                         \
        int _k0 = (ch) * 32;                                                  \
        bool ok  = nval && (_k0 + lk < NM);                                   \
        bool ok2 = nval && (_k0 + lk + 8 < NM);                               \
        uint32_t dB = sb + (s) * PSTG2 + 10240 + sA;                          \
        cpasync16(dB,              Fh + _k0,     ok);                         \
        cpasync16(dB + 16,         Fh + _k0 + 8, ok2);                        \
        cpasync16(dB + 10240,      Fl + _k0,     ok);                         \
        cpasync16(dB + 10240 + 16, Fl + _k0 + 8, ok2);                        \
    }

#define STSA(s)                                                               \
    {                                                                         \
        char* stg = sm + (s) * PSTG2;                                         \
        _Pragma("unroll")                                                     \
        for (int i = 0; i < 4; i++) {                                         \
            float e0 = dok[i] ? s2 * __expf(cexp * dv[i].x) : 0.f;            \
            float e1 = dok[i] ? s2 * __expf(cexp * dv[i].y) : 0.f;            \
            float e2 = dok[i] ? s2 * __expf(cexp * dv[i].z) : 0.f;            \
            float e3 = dok[i] ? s2 * __expf(cexp * dv[i].w) : 0.f;            \
            uint32_t h01 = pack2h(e0, e1);                                    \
            uint32_t h23 = pack2h(e2, e3);                                    \
            *(uint2*)(stg + sA + i * 8) = make_uint2(h01, h23);               \
        }                                                                     \
    }

    const int wm = (wid & 3) * 32, wn = (wid >> 2) * 64;
    const uint32_t aAoff = (uint32_t)((wm + (lane & 15)) * 40 + ((lane >> 4) & 1) * 8) * 2;
    const uint32_t aBoff = (uint32_t)((wn + ((lane >> 4) << 3) + (lane & 7)) * 40
                                      + ((lane >> 3) & 1) * 8) * 2;

    float acc[2][8][4];
#pragma unroll
    for (int a = 0; a < 2; a++)
#pragma unroll
        for (int b = 0; b < 8; b++)
#pragma unroll
            for (int d = 0; d < 4; d++) acc[a][b][d] = 0.f;

    LOADD(0);
    ISSUEF(0, 0); CP_COMMIT();
    STSA(0);
    LOADD(1);
    ISSUEF(1, 1); CP_COMMIT();
    CP_WAIT1();
    __syncthreads();

    for (int ch = 0; ch < NCHUNK; ++ch) {
        const int s = ch & 1;
        const uint32_t base = sb + s * PSTG2;

#pragma unroll
        for (int kst = 0; kst < 2; ++kst) {
            uint32_t ah[2][4];
#pragma unroll
            for (int mt = 0; mt < 2; ++mt) {
                uint32_t o = aAoff + mt * 1280 + kst * 32;
                ldx4(ah[mt], base + o);
            }
#pragma unroll
            for (int nh = 0; nh < 2; ++nh) {
                uint32_t bh[2][4], bl[2][4];
#pragma unroll
                for (int ng = 0; ng < 2; ++ng) {
                    uint32_t o = aBoff + nh * 2560 + ng * 1280 + kst * 32;
                    ldx4(bh[ng], base + 10240 + o);
                    ldx4(bl[ng], base + 20480 + o);
                }
#pragma unroll
                for (int mt = 0; mt < 2; mt++)
#pragma unroll
                    for (int nt = 0; nt < 4; nt++) {
                        float* cc = acc[mt][nh * 4 + nt];
                        uint32_t b0h = bh[nt >> 1][(nt & 1) * 2];
                        uint32_t b1h = bh[nt >> 1][(nt & 1) * 2 + 1];
                        uint32_t b0l = bl[nt >> 1][(nt & 1) * 2];
                        uint32_t b1l = bl[nt >> 1][(nt & 1) * 2 + 1];
                        mma16816h(cc, ah[mt], b0h, b1h);
                        mma16816h(cc, ah[mt], b0l, b1l);
                    }
            }
        }
        __syncthreads();

        if (ch + 2 < NCHUNK) ISSUEF(ch + 2, s);
        CP_COMMIT();
        if (ch + 1 < NCHUNK) STSA(s ^ 1);
        if (ch + 2 < NCHUNK) LOADD(ch + 2);
        CP_WAIT1();
        __syncthreads();
    }

    // epilogue: transpose via smem staging
    float* stg = (float*)sm;  // [128 n][68 m] per 64-m half = 34816 B
#pragma unroll
    for (int h = 0; h < 2; ++h) {
        __syncthreads();
        if (((wid & 3) >> 1) == h) {
            const int rb = wm - h * 64 + (lane >> 2);
            const int cb = 2 * (lane & 3);
#pragma unroll
            for (int mt = 0; mt < 2; mt++)
#pragma unroll
                for (int nt = 0; nt < 8; nt++) {
                    int r = rb + mt * 16;
                    int c = wn + ((nt >> 2) * 32) + ((nt & 3) * 8) + cb;
                    stg[(c + 0) * 68 + r]     = acc[mt][nt][0];
                    stg[(c + 1) * 68 + r]     = acc[mt][nt][1];
                    stg[(c + 0) * 68 + r + 8] = acc[mt][nt][2];
                    stg[(c + 1) * 68 + r + 8] = acc[mt][nt][3];
                }
        }
        __syncthreads();
#pragma unroll 4
        for (int it = 0; it < 32; ++it) {
            int nr = it * 4 + (tid >> 6);
            int mc = tid & 63;
            int j = j0 + nr, m = m0 + h * 64 + mc;
            if (j < ND && m < NM) g_Pt[(size_t)j * NM + m] = stg[nr * 68 + mc];
        }
    }
}

// =====================================================================
// kBmma: Bpart[z] = F @ P   (fp16 3-pass: hh + hl + lh)
// =====================================================================
__global__ __launch_bounds__(256, 1) void kBmma() {
    __shared__ __align__(16) char sm[SM_BYTES];
    __half* Ahi = (__half*)sm;
    __half* Alo = (__half*)(sm + A_LO_OFF);
    __half* Bhi = (__half*)(sm + B_HI_OFF);
    __half* Blo = (__half*)(sm + B_LO_OFF);
    const uint32_t sb = smem_u32(sm);

    const int tid = threadIdx.x, lane = tid & 31, wid = tid >> 5;
    const int i0 = blockIdx.x * 128, j0 = blockIdx.y * 128;
    const int z = blockIdx.z;
    const int c0 = z * 40;
    const int c1 = min(NCHUNK, c0 + 40);

    const int lr = tid >> 1, lk = (tid & 1) * 16;
    const bool ival = (i0 + lr) < ND;
    const bool jval = (j0 + lr) < ND;
    const __half* Fh = g_Fhh + (size_t)(i0 + lr) * NM + lk;
    const __half* Fl = g_Fhl + (size_t)(i0 + lr) * NM + lk;
    const float* Pp = g_Pt + (size_t)(j0 + lr) * NM + lk;

    float4 pv[4];
    bool pok[4];
    uint4 fh[2], fl[2];

#define LOADCH_B(k0)                                                          \
    {                                                                         \
        _Pragma("unroll")                                                     \
        for (int i = 0; i < 2; i++) {                                         \
            int kk = (k0) + lk + i * 8;                                       \
            bool ok = ival && (kk < NM);                                      \
            fh[i] = ok ? *(const uint4*)(Fh + (k0) + i * 8) : make_uint4(0, 0, 0, 0); \
            fl[i] = ok ? *(const uint4*)(Fl + (k0) + i * 8) : make_uint4(0, 0, 0, 0); \
        }                                                                     \
        _Pragma("unroll")                                                     \
        for (int i = 0; i < 4; i++) {                                         \
            int kk = (k0) + lk + i * 4;                                       \
            pok[i] = jval && (kk < NM);                                       \
            pv[i] = pok[i] ? *(const float4*)(Pp + (k0) + i * 4)              \
                           : make_float4(0.f, 0.f, 0.f, 0.f);                 \
        }                                                                     \
    }

    const int sA = lr * 40 + lk;
    const int wm = (wid & 3) * 32, wn = (wid >> 2) * 64;
    const uint32_t aAoff = (uint32_t)((wm + (lane & 15)) * 40 + ((lane >> 4) & 1) * 8) * 2;
    const uint32_t aBoff = (uint32_t)((wn + ((lane >> 4) << 3) + (lane & 7)) * 40
                                      + ((lane >> 3) & 1) * 8) * 2;

    float acc[2][8][4];
#pragma unroll
    for (int a = 0; a < 2; a++)
#pragma unroll
        for (int b = 0; b < 8; b++)
#pragma unroll
            for (int d = 0; d < 4; d++) acc[a][b][d] = 0.f;

    LOADCH_B(c0 * 32);

    for (int ch = c0; ch < c1; ++ch) {
        *(uint4*)(Ahi + sA) = fh[0];
        *(uint4*)(Ahi + sA + 8) = fh[1];
        *(uint4*)(Alo + sA) = fl[0];
        *(uint4*)(Alo + sA + 8) = fl[1];
#pragma unroll
        for (int i = 0; i < 4; i++) {
            uint32_t h01, l01, h23, l23;
            split2h(pv[i].x, pv[i].y, h01, l01);
            split2h(pv[i].z, pv[i].w, h23, l23);
            *(uint2*)(Bhi + sA + i * 4) = make_uint2(h01, h23);
            *(uint2*)(Blo + sA + i * 4) = make_uint2(l01, l23);
        }
        __syncthreads();

        if (ch + 1 < c1) LOADCH_B((ch + 1) * 32);

#pragma unroll
        for (int kst = 0; kst < 2; ++kst) {
            uint32_t ah[2][4], al[2][4];
#pragma unroll
            for (int mt = 0; mt < 2; ++mt) {
                uint32_t o = aAoff + mt * 1280 + kst * 32;
                ldx4(ah[mt], sb + o);
                ldx4(al[mt], sb + A_LO_OFF + o);
            }
#pragma unroll
            for (int nh = 0; nh < 2; ++nh) {
                uint32_t bh[2][4], bl[2][4];
#pragma unroll
                for (int ng = 0; ng < 2; ++ng) {
                    uint32_t o = aBoff + nh * 2560 + ng * 1280 + kst * 32;
                    ldx4(bh[ng], sb + B_HI_OFF + o);
                    ldx4(bl[ng], sb + B_LO_OFF + o);
                }
#pragma unroll
                for (int mt = 0; mt < 2; mt++)
#pragma unroll
                    for (int nt = 0; nt < 4; nt++) {
                        float* cc = acc[mt][nh * 4 + nt];
                        uint32_t b0h = bh[nt >> 1][(nt & 1) * 2];
                        uint32_t b1h = bh[nt >> 1][(nt & 1) * 2 + 1];
                        uint32_t b0l = bl[nt >> 1][(nt & 1) * 2];
                        uint32_t b1l = bl[nt >> 1][(nt & 1) * 2 + 1];
                        mma16816h(cc, ah[mt], b0h, b1h);
                        mma16816h(cc, ah[mt], b0l, b1l);
                        mma16816h(cc, al[mt], b0h, b1h);
                    }
            }
        }
        __syncthreads();
    }

    float* Bp = g_Bpart + (size_t)z * ND * ND;
    const int rb = i0 + wm + (lane >> 2);
    const int cb = j0 + wn + 2 * (lane & 3);
#pragma unroll
    for (int mt = 0; mt < 2; mt++)
#pragma unroll
        for (int nt = 0; nt < 8; nt++) {
            int i = rb + mt * 16;
            int c = cb + (nt >> 2) * 32 + (nt & 3) * 8;
            if (c < ND) {
                if (i < ND)
                    *(float2*)(Bp + (size_t)i * ND + c) = make_float2(acc[mt][nt][0], acc[mt][nt][1]);
                if (i + 8 < ND)
                    *(float2*)(Bp + (size_t)(i + 8) * ND + c) = make_float2(acc[mt][nt][2], acc[mt][nt][3]);
            }
        }
}

// combine k-split partials + data_cov into Aaug
__global__ void kC(const float* __restrict__ dcov) {
    int idx = blockIdx.x * 256 + threadIdx.x;
    if (idx >= ND * ND) return;
    float s = dcov[idx];
#pragma unroll
    for (int zz = 0; zz < KSB; zz++) s += g_Bpart[(size_t)zz * ND * ND + idx];
    int i = idx / ND, j = idx - i * ND;
    g_Aaug[i * LDA + j] = s;
}

// prior misfit r = d_obs - m0 * rowsum(F)
__global__ __launch_bounds__(256) void kR(const float* __restrict__ F,
                                          const float* __restrict__ dobs,
                                          const float* __restrict__ m0p) {
    __shared__ float red[8];
    const int i = blockIdx.x;
    const float* row = F + (size_t)i * NM;
    float s = 0.f;
    for (int t = threadIdx.x; t < NM; t += 256) s += row[t];
#pragma unroll
    for (int o = 16; o; o >>= 1) s += __shfl_down_sync(0xffffffffu, s, o);
    if ((threadIdx.x & 31) == 0) red[threadIdx.x >> 5] = s;
    __syncthreads();
    if (threadIdx.x == 0) {
        float tot = 0.f;
#pragma unroll
        for (int w = 0; w < 8; w++) tot += red[w];
        float r = dobs[i] - m0p[0] * tot;
        g_Aaug[i * LDA + ND] = r;
        g_rorig[i] = r;
    }
}

// =====================================================================
// kLU: panel factor + fused TRSM.
// R17 FIX: panel stored with PADDED row stride PWP=33. The old stride-32
// layout put every warp lane (consecutive rows) on the SAME bank ->
// 32-way conflict on every LDS/STS of the rank-1 update and pivot scan
// (~3ms total across the chain). (i*33+c) mod 32 = (i+c) mod 32 ->
// consecutive rows hit consecutive banks -> conflict-free.
// =====================================================================
__global__ __launch_bounds__(512) void kLU(int p0, int pw) {
    extern __shared__ float dyn[];
    const int tid = threadIdx.x, lane = tid & 31, wid = tid >> 5;
    const int nrows = ND - p0;
    float* sp  = dyn;                         // nrows x PWP padded panel
    int*   srp = (int*)(dyn + nrows * PWP);   // local slice of g_rp

    __shared__ float s_pv;
    __shared__ float Ls[32][33];              // zero-padded L11 for fused TRSM

    for (int i = tid; i < nrows; i += 512) srp[i] = g_rp[p0 + i];
    __syncthreads();
    for (int idx = tid; idx < nrows * pw; idx += 512) {
        int i = idx / pw, c = idx % pw;
        sp[i * PWP + c] = g_Aaug[(size_t)srp[i] * LDA + p0 + c];
    }

    for (int j = 0; j < pw; j++) {
        __syncthreads();                      // panel state ready for column j
        if (wid == 0) {
            float best = -1.f; int bi = j;
            for (int i = j + lane; i < nrows; i += 32) {
                float v = fabsf(sp[i * PWP + j]);
                if (v > best) { best = v; bi = i; }
            }
#pragma unroll
            for (int o = 16; o; o >>= 1) {
                float ov = __shfl_down_sync(0xffffffffu, best, o);
                int   oi = __shfl_down_sync(0xffffffffu, bi,   o);
                if (ov > best) { best = ov; bi = oi; }
            }
            int piv = __shfl_sync(0xffffffffu, bi, 0);
            if (piv != j) {
                if (lane < pw) {
                    float t = sp[j * PWP + lane];
                    sp[j * PWP + lane] = sp[piv * PWP + lane];
                    sp[piv * PWP + lane] = t;
                }
                if (lane == 0) { int t = srp[j]; srp[j] = srp[piv]; srp[piv] = t; }
            }
            __syncwarp();
            if (lane == 0) s_pv = sp[j * PWP + j];
        }
        __syncthreads();                      // pivot + swap visible
        const float inv = 1.f / s_pv;
        for (int i = j + 1 + tid; i < nrows; i += 512) {
            float lij = sp[i * PWP + j] * inv;
            sp[i * PWP + j] = lij;
            for (int jj = j + 1; jj < pw; jj++)
                sp[i * PWP + jj] -= lij * sp[j * PWP + jj];
        }
    }
    __syncthreads();

    // write back panel + permutation; stage L11 into padded Ls
    for (int idx = tid; idx < 32 * 33; idx += 512) ((float*)Ls)[idx] = 0.f;
    __syncthreads();
    for (int idx = tid; idx < nrows * pw; idx += 512) {
        int i = idx / pw, c = idx % pw;
        g_Aaug[(size_t)srp[i] * LDA + p0 + c] = sp[i * PWP + c];
    }
    for (int i = tid; i < nrows; i += 512) g_rp[p0 + i] = srp[i];
    for (int idx = tid; idx < pw * pw; idx += 512)
        Ls[idx / pw][idx % pw] = sp[(idx / pw) * PWP + (idx % pw)];
    __syncthreads();

    // fused TRSM: U12 = L11^{-1} A12 over trailing cols incl. rhs (col ND)
    for (int c = p0 + pw + tid; c <= ND; c += 512) {
        float v[32];
#pragma unroll
        for (int i = 0; i < 32; i++)
            v[i] = (i < pw) ? g_Aaug[(size_t)srp[i] * LDA + c] : 0.f;
#pragma unroll
        for (int k = 0; k < 32; k++) {
            if (k >= pw) break;
            float vk = v[k];
#pragma unroll
            for (int i = 0; i < 32; i++)
                if (i > k) v[i] -= Ls[i][k] * vk;
        }
#pragma unroll
        for (int i = 0; i < 32; i++)
            if (i < pw) g_Aaug[(size_t)srp[i] * LDA + c] = v[i];
    }
}

// A22 -= L21 @ U12  (rows via g_rp)
__global__ __launch_bounds__(256) void kG(int p0, int pw) {
    __shared__ float Ls[32][33];
    __shared__ float Us[32][36];
    __shared__ int   rmap[32];
    const int tid = threadIdx.x;
    const int r0  = p0 + pw;
    const int gi0 = r0 + blockIdx.x * 32;
    const int gj0 = r0 + blockIdx.y * 32;

    if (tid < 32) rmap[tid] = (gi0 + tid < ND) ? g_rp[gi0 + tid] : 0;
    __syncthreads();

    for (int idx = tid; idx < 32 * 32; idx += 256) {
        int i = idx >> 5, k = idx & 31;
        float v = 0.f;
        if (k < pw && gi0 + i < ND) v = g_Aaug[(size_t)rmap[i] * LDA + p0 + k];
        Ls[i][k] = v;
    }
    for (int idx = tid; idx < 32 * 32; idx += 256) {
        int k = idx >> 5, jn = idx & 31;
        float v = 0.f;
        if (k < pw && gj0 + jn <= ND) v = g_Aaug[(size_t)g_rp[p0 + k] * LDA + gj0 + jn];
        Us[k][jn] = v;
    }
    __syncthreads();

    const int mi = tid >> 3;
    const int nj = (tid & 7) * 4;
    float a0 = 0.f, a1 = 0.f, a2 = 0.f, a3 = 0.f;
    for (int k = 0; k < pw; k++) {
        float a = Ls[mi][k];
        a0 += a * Us[k][nj + 0];
        a1 += a * Us[k][nj + 1];
        a2 += a * Us[k][nj + 2];
        a3 += a * Us[k][nj + 3];
    }
    const int gi = gi0 + mi;
    if (gi < ND) {
        float* rowp = g_Aaug + (size_t)rmap[mi] * LDA;
        if (gj0 + nj + 0 <= ND) rowp[gj0 + nj + 0] -= a0;
        if (gj0 + nj + 1 <= ND) rowp[gj0 + nj + 1] -= a1;
        if (gj0 + nj + 2 <= ND) rowp[gj0 + nj + 2] -= a2;
        if (gj0 + nj + 3 <= ND) rowp[gj0 + nj + 3] -= a3;
    }
}

// back-substitution (warp-shuffle diag blocks) -> x0; logdet -> g_ld
__global__ __launch_bounds__(512) void kBack(void) {
    __shared__ float x[ND];
    __shared__ float ub[32][33];
    __shared__ float red[16];
    const int tid = threadIdx.x;

    for (int i = tid; i < ND; i += 512) x[i] = g_Aaug[(size_t)g_rp[i] * LDA + ND];
    float ld = 0.f;
    for (int k = tid; k < ND; k += 512) ld += logf(fabsf(g_Aaug[(size_t)g_rp[k] * LDA + k]));
    __syncthreads();

    for (int pb = NPANEL - 1; pb >= 0; pb--) {
        const int p0 = pb * NB;
        const int pw = (pb == NPANEL - 1) ? (ND - p0) : NB;
        for (int idx = tid; idx < pw * pw; idx += 512)
            ub[idx / pw][idx % pw] = g_Aaug[(size_t)g_rp[p0 + idx / pw] * LDA + p0 + (idx % pw)];
        __syncthreads();
        if (tid < 32) {
            float xi = (tid < pw) ? x[p0 + tid] : 0.f;
            for (int j = pw - 1; j >= 0; j--) {
                if (tid == j) xi /= ub[j][j];
                float xj = __shfl_sync(0xffffffffu, xi, j);
                if (tid < j) xi -= ub[tid][j] * xj;
            }
            if (tid < pw) x[p0 + tid] = xi;
        }
        __syncthreads();
        for (int i = tid; i < p0; i += 512) {
            float s = 0.f;
            for (int j = 0; j < pw; j++)
                s += g_Aaug[(size_t)g_rp[i] * LDA + p0 + j] * x[p0 + j];
            x[i] -= s;
        }
        __syncthreads();
    }

#pragma unroll
    for (int o = 16; o; o >>= 1) ld += __shfl_down_sync(0xffffffffu, ld, o);
    if ((tid & 31) == 0) red[tid >> 5] = ld;
    __syncthreads();
    if (tid == 0) {
        float tl = 0.f;
        for (int w = 0; w < 16; w++) tl += red[w];
        g_ld[0] = tl;
    }
    for (int i = tid; i < ND; i += 512) g_tmp[i] = x[i];
}

// ===================== iterative refinement: exact fp32 operator =============
__global__ __launch_bounds__(256) void kAy(const float* __restrict__ F) {
    __shared__ float sx[ND];
    const int tid = threadIdx.x;
    for (int i = tid; i < ND; i += 256) sx[i] = g_tmp[i];
    __syncthreads();
    const int m = blockIdx.x * 256 + tid;
    if (m >= NM) return;
    float s = 0.f;
#pragma unroll 4
    for (int i = 0; i < ND; i++) s += F[(size_t)i * NM + m] * sx[i];
    g_y[m] = s;
}

__global__ __launch_bounds__(256) void kAz(const float* __restrict__ Dm,
                                           const float* __restrict__ lsp,
                                           const float* __restrict__ sgp) {
    const int tid = threadIdx.x, lane = tid & 31, warp = tid >> 5;
    const int row = blockIdx.x * 8 + warp;
    if (row >= NM) return;
    const float l = lsp[0];
    const float c = -0.5f / (l * l);
    const float s2 = sgp[0] * sgp[0];
    const float* dr = Dm + (size_t)row * NM;
    float s = 0.f;
    for (int k = lane; k < NM; k += 32) s += __expf(c * dr[k]) * __ldg(&g_y[k]);
#pragma unroll
    for (int o = 16; o; o >>= 1) s += __shfl_down_sync(0xffffffffu, s, o);
    if (lane == 0) g_z[row] = s2 * s;
}

__global__ __launch_bounds__(256) void kAw(const float* __restrict__ F,
                                           const float* __restrict__ dcov) {
    __shared__ float red[8];
    const int i = blockIdx.x;
    const int tid = threadIdx.x;
    float s = 0.f;
    const float* fr = F + (size_t)i * NM;
    for (int m = tid; m < NM; m += 256) s += fr[m] * g_z[m];
    const float* cr = dcov + (size_t)i * ND;
    for (int j = tid; j < ND; j += 256) s += cr[j] * g_tmp[j];
#pragma unroll
    for (int o = 16; o; o >>= 1) s += __shfl_down_sync(0xffffffffu, s, o);
    if ((tid & 31) == 0) red[tid >> 5] = s;
    __syncthreads();
    if (tid == 0) {
        float tot = 0.f;
#pragma unroll
        for (int w = 0; w < 8; w++) tot += red[w];
        g_resid[i] = g_rorig[i] - tot;
    }
}

// solve LU dx = P resid; x += dx; out[0] = logdet + r^T x; g_tmp = x
__global__ __launch_bounds__(512) void kSolve(float* __restrict__ out) {
    __shared__ float x[ND];
    __shared__ float Bs[32][33];
    __shared__ float red[16];
    const int tid = threadIdx.x;

    for (int i = tid; i < ND; i += 512) x[i] = g_resid[g_rp[i]];
    __syncthreads();

    for (int pb = 0; pb < NPANEL; pb++) {
        const int p0 = pb * NB;
        const int pw = (pb == NPANEL - 1) ? (ND - p0) : NB;
        for (int idx = tid; idx < pw * pw; idx += 512)
            Bs[idx / pw][idx % pw] = g_Aaug[(size_t)g_rp[p0 + idx / pw] * LDA + p0 + (idx % pw)];
        __syncthreads();
        if (tid < 32) {
            float xi = (tid < pw) ? x[p0 + tid] : 0.f;
            for (int j = 0; j < pw; j++) {
                float xj = __shfl_sync(0xffffffffu, xi, j);
                if (tid > j && tid < pw) xi -= Bs[tid][j] * xj;
            }
            if (tid < pw) x[p0 + tid] = xi;
        }
        __syncthreads();
        for (int i = p0 + pw + tid; i < ND; i += 512) {
            float s = 0.f;
            for (int j = 0; j < pw; j++)
                s += g_Aaug[(size_t)g_rp[i] * LDA + p0 + j] * x[p0 + j];
            x[i] -= s;
        }
        __syncthreads();
    }

    for (int pb = NPANEL - 1; pb >= 0; pb--) {
        const int p0 = pb * NB;
        const int pw = (pb == NPANEL - 1) ? (ND - p0) : NB;
        for (int idx = tid; idx < pw * pw; idx += 512)
            Bs[idx / pw][idx % pw] = g_Aaug[(size_t)g_rp[p0 + idx / pw] * LDA + p0 + (idx % pw)];
        __syncthreads();
        if (tid < 32) {
            float xi = (tid < pw) ? x[p0 + tid] : 0.f;
            for (int j = pw - 1; j >= 0; j--) {
                if (tid == j) xi /= Bs[j][j];
                float xj = __shfl_sync(0xffffffffu, xi, j);
                if (tid < j) xi -= Bs[tid][j] * xj;
            }
            if (tid < pw) x[p0 + tid] = xi;
        }
        __syncthreads();
        for (int i = tid; i < p0; i += 512) {
            float s = 0.f;
            for (int j = 0; j < pw; j++)
                s += g_Aaug[(size_t)g_rp[i] * LDA + p0 + j] * x[p0 + j];
            x[i] -= s;
        }
        __syncthreads();
    }

    float dp = 0.f;
    for (int i = tid; i < ND; i += 512) {
        float v = g_tmp[i] + x[i];
        x[i] = v;
        dp += g_rorig[i] * v;
    }
#pragma unroll
    for (int o = 16; o; o >>= 1) dp += __shfl_down_sync(0xffffffffu, dp, o);
    if ((tid & 31) == 0) red[tid >> 5] = dp;
    __syncthreads();
    if (tid == 0) {
        float td = 0.f;
#pragma unroll
        for (int w = 0; w < 16; w++) td += red[w];
        out[0] = g_ld[0] + td;
    }
    for (int i = tid; i < ND; i += 512) g_tmp[i] = x[i];
}

// m_posterior = m0 + P @ x, via Pt (thread per model row, coalesced)
__global__ __launch_bounds__(256) void kM(float* __restrict__ out,
                                          const float* __restrict__ m0p) {
    __shared__ float sx[ND];
    const int tid = threadIdx.x;
    for (int i = tid; i < ND; i += 256) sx[i] = g_tmp[i];
    __syncthreads();
    const int m = blockIdx.x * 256 + tid;
    if (m >= NM) return;
    float s = 0.f;
#pragma unroll 4
    for (int j = 0; j < ND; j++) s += g_Pt[(size_t)j * NM + m] * sx[j];
    out[1 + m] = m0p[0] + s;
}

// =====================================================================
extern "C" void kernel_launch(void* const* d_in, const int* in_sizes, int n_in,
                              void* d_out, int out_size) {
    const float* D    = (const float*)d_in[0];
    const float* F    = (const float*)d_in[1];
    const float* dobs = (const float*)d_in[2];
    const float* dcov = (const float*)d_in[3];
    const float* m0p  = (const float*)d_in[4];
    const float* lsp  = (const float*)d_in[5];
    const float* sgp  = (const float*)d_in[6];
    float* out = (float*)d_out;

    cudaFuncSetAttribute(kLU, cudaFuncAttributeMaxDynamicSharedMemorySize,
                         ND * PWP * 4 + ND * 4);
    cudaFuncSetAttribute(kPmma, cudaFuncAttributeMaxDynamicSharedMemorySize, PM_SMEM);

    // kPmma is launch #4 -> ncu capture lands on it
    kFsplit<<<(ND * NM + 255) / 256, 256>>>(F);
    kR<<<ND, 256>>>(F, dobs, m0p);
    kInit<<<(ND + 255) / 256, 256>>>();
    kPmma<<<dim3(79, 5), 256, PM_SMEM>>>(D, lsp, sgp);
    kBmma<<<dim3(5, 5, KSB), 256>>>();
    kC<<<(ND * ND + 255) / 256, 256>>>(dcov);

    for (int p = 0; p < NPANEL; p++) {
        const int p0 = p * NB;
        const int pw = (p == NPANEL - 1) ? (ND - p0) : NB;
        const int nrows = ND - p0;
        kLU<<<1, 512, nrows * PWP * 4 + nrows * 4>>>(p0, pw);
        const int m = ND - (p0 + pw);
        const int tcols = ND + 1 - (p0 + pw);
        if (m > 0)
            kG<<<dim3((m + 31) / 32, (tcols + 31) / 32), 256>>>(p0, pw);
    }

    kBack<<<1, 512>>>();

    // TWO refinement iterations (operator error ~3e-4 from fp16 2-pass P)
    for (int it = 0; it < 2; ++it) {
        kAy<<<(NM + 255) / 256, 256>>>(F);
        kAz<<<(NM + 7) / 8, 256>>>(D, lsp, sgp);
        kAw<<<ND, 256>>>(F, dcov);
        kSolve<<<1, 512>>>(out);
    }

    kM<<<(NM + 255) / 256, 256>>>(out, m0p);
}